// round 14
// baseline (speedup 1.0000x reference)
#include <cuda_runtime.h>
#include <cuda_fp16.h>
#include <math.h>
#include <stdint.h>

// ---------------- problem constants ----------------
#define DD     1024
#define LL     2048
#define BB     4
#define NH     16
#define DH     64
#define SSEL   5
#define WWIN   128
#define BKBLK  32
#define NB     64          // L / BK
#define NTOK   8192        // B*L
#define MKV    2560        // B*S*W
#define NKEY   640         // S*W keys per batch
#define DFFN   4096

// ---------------- scratch (device globals; no allocations allowed) --------
__device__ __half g_h16 [NTOK * DD];
__device__ __half g_kv16[MKV  * DD];
__device__ __half g_q16 [NTOK * DD];
__device__ __half g_k16 [MKV  * DD];
__device__ __half g_v16 [MKV  * DD];
__device__ __half g_att16[NTOK * DD];
__device__ float  g_x2  [NTOK * DD];
__device__ __half g_h2_16[NTOK * DD];
__device__ __half g_ff16 [NTOK * DFFN];
__device__ __half g_w16  [12582912];     // fp16 weights: ipw | opw | w_fc | w_proj
__device__ float  g_logits[BB * NB];

#define W16_IPW   0
#define W16_OPW   3145728
#define W16_WFC   4194304
#define W16_WPROJ 8388608
#define W16_TOTAL 12582912

// ---------------- helpers ----------------
__device__ __forceinline__ void mma_f16(float* d, const uint32_t* a, const uint32_t* b) {
    asm volatile(
        "mma.sync.aligned.m16n8k16.row.col.f32.f16.f16.f32 "
        "{%0,%1,%2,%3}, {%4,%5,%6,%7}, {%8,%9}, {%0,%1,%2,%3};\n"
        : "+f"(d[0]), "+f"(d[1]), "+f"(d[2]), "+f"(d[3])
        : "r"(a[0]), "r"(a[1]), "r"(a[2]), "r"(a[3]), "r"(b[0]), "r"(b[1]));
}

__device__ __forceinline__ void ldsm4(uint32_t& r0, uint32_t& r1, uint32_t& r2, uint32_t& r3,
                                      uint32_t addr) {
    asm volatile("ldmatrix.sync.aligned.m8n8.x4.shared.b16 {%0,%1,%2,%3}, [%4];"
                 : "=r"(r0), "=r"(r1), "=r"(r2), "=r"(r3) : "r"(addr));
}
__device__ __forceinline__ void ldsm4t(uint32_t& r0, uint32_t& r1, uint32_t& r2, uint32_t& r3,
                                       uint32_t addr) {
    asm volatile("ldmatrix.sync.aligned.m8n8.x4.trans.shared.b16 {%0,%1,%2,%3}, [%4];"
                 : "=r"(r0), "=r"(r1), "=r"(r2), "=r"(r3) : "r"(addr));
}

__device__ __forceinline__ void cp16(void* s, const void* g) {
    unsigned sa = (unsigned)__cvta_generic_to_shared(s);
    asm volatile("cp.async.cg.shared.global [%0], [%1], 16;\n" :: "r"(sa), "l"(g));
}
__device__ __forceinline__ void cp_commit() { asm volatile("cp.async.commit_group;\n"); }
__device__ __forceinline__ void cp_wait0()  { asm volatile("cp.async.wait_group 0;\n"); }
__device__ __forceinline__ void cp_wait1()  { asm volatile("cp.async.wait_group 1;\n"); }
__device__ __forceinline__ void cp_wait2()  { asm volatile("cp.async.wait_group 2;\n"); }

// ---------------- fused fp32 -> fp16 weight conversion ----------------
__global__ void f2h_all_kernel(const float* __restrict__ ipw,
                               const float* __restrict__ opw,
                               const float* __restrict__ wfc,
                               const float* __restrict__ wproj,
                               __half* __restrict__ w16) {
    int i = (blockIdx.x * blockDim.x + threadIdx.x) * 4;
    if (i >= W16_TOTAL) return;
    const float* src;
    if (i < W16_OPW)        src = ipw + i;
    else if (i < W16_WFC)   src = opw + (i - W16_OPW);
    else if (i < W16_WPROJ) src = wfc + (i - W16_WFC);
    else                    src = wproj + (i - W16_WPROJ);
    float4 v = *reinterpret_cast<const float4*>(src);
    __half2* d = reinterpret_cast<__half2*>(w16 + i);
    d[0] = __floats2half2_rn(v.x, v.y);
    d[1] = __floats2half2_rn(v.z, v.w);
}

// ---------- LN1 + fused saliency: one block per token ----------
__global__ void ln1_sal_kernel(const float* __restrict__ x,
                               const float* __restrict__ gam,
                               const float* __restrict__ bet,
                               const float* __restrict__ w_sal,
                               __half* __restrict__ out16,
                               float* __restrict__ logits) {
    __shared__ float red[8];
    const int row = blockIdx.x;
    const int t = threadIdx.x;  // 256
    const float4* xr = reinterpret_cast<const float4*>(x) + (size_t)row * (DD / 4);
    float4 v = xr[t];

    float s = v.x + v.y + v.z + v.w;
    #pragma unroll
    for (int o = 16; o; o >>= 1) s += __shfl_down_sync(0xffffffffu, s, o);
    if ((t & 31) == 0) red[t >> 5] = s;
    __syncthreads();
    float tot = red[0] + red[1] + red[2] + red[3] + red[4] + red[5] + red[6] + red[7];
    const float mean = tot * (1.0f / DD);
    __syncthreads();

    float dx = v.x - mean, dy = v.y - mean, dz = v.z - mean, dw = v.w - mean;
    float sq = dx * dx + dy * dy + dz * dz + dw * dw;
    #pragma unroll
    for (int o = 16; o; o >>= 1) sq += __shfl_down_sync(0xffffffffu, sq, o);
    if ((t & 31) == 0) red[t >> 5] = sq;
    __syncthreads();
    float var = (red[0] + red[1] + red[2] + red[3] + red[4] + red[5] + red[6] + red[7]) * (1.0f / DD);
    const float r = rsqrtf(var + 1e-5f);

    const float4 gg = reinterpret_cast<const float4*>(gam)[t];
    const float4 bb = reinterpret_cast<const float4*>(bet)[t];
    float4 o4;
    o4.x = dx * r * gg.x + bb.x;
    o4.y = dy * r * gg.y + bb.y;
    o4.z = dz * r * gg.z + bb.z;
    o4.w = dw * r * gg.w + bb.w;
    __half2* d = reinterpret_cast<__half2*>(out16 + (size_t)row * DD + t * 4);
    d[0] = __floats2half2_rn(o4.x, o4.y);
    d[1] = __floats2half2_rn(o4.z, o4.w);

    const float4 ws = reinterpret_cast<const float4*>(w_sal)[t];
    float dsal = o4.x * ws.x + o4.y * ws.y + o4.z * ws.z + o4.w * ws.w;
    __syncthreads();
    #pragma unroll
    for (int o = 16; o; o >>= 1) dsal += __shfl_down_sync(0xffffffffu, dsal, o);
    if ((t & 31) == 0) red[t >> 5] = dsal;
    __syncthreads();
    if (t == 0) {
        float dtot = red[0] + red[1] + red[2] + red[3] + red[4] + red[5] + red[6] + red[7];
        atomicAdd(&logits[row >> 5], dtot * (1.0f / BKBLK));
    }
}

// ---------------- LayerNorm (LN2): one block per token, fp16 out ----------
__global__ void ln2_kernel(const float* __restrict__ x,
                           const float* __restrict__ gam,
                           const float* __restrict__ bet,
                           __half* __restrict__ out16) {
    __shared__ float red[8];
    const int row = blockIdx.x;
    const int t = threadIdx.x;  // 256
    const float4* xr = reinterpret_cast<const float4*>(x) + (size_t)row * (DD / 4);
    float4 v = xr[t];

    float s = v.x + v.y + v.z + v.w;
    #pragma unroll
    for (int o = 16; o; o >>= 1) s += __shfl_down_sync(0xffffffffu, s, o);
    if ((t & 31) == 0) red[t >> 5] = s;
    __syncthreads();
    float tot = red[0] + red[1] + red[2] + red[3] + red[4] + red[5] + red[6] + red[7];
    const float mean = tot * (1.0f / DD);
    __syncthreads();

    float dx = v.x - mean, dy = v.y - mean, dz = v.z - mean, dw = v.w - mean;
    float sq = dx * dx + dy * dy + dz * dz + dw * dw;
    #pragma unroll
    for (int o = 16; o; o >>= 1) sq += __shfl_down_sync(0xffffffffu, sq, o);
    if ((t & 31) == 0) red[t >> 5] = sq;
    __syncthreads();
    float var = (red[0] + red[1] + red[2] + red[3] + red[4] + red[5] + red[6] + red[7]) * (1.0f / DD);
    const float r = rsqrtf(var + 1e-5f);

    const float4 gg = reinterpret_cast<const float4*>(gam)[t];
    const float4 bb = reinterpret_cast<const float4*>(bet)[t];
    __half2* d = reinterpret_cast<__half2*>(out16 + (size_t)row * DD + t * 4);
    d[0] = __floats2half2_rn(dx * r * gg.x + bb.x, dy * r * gg.y + bb.y);
    d[1] = __floats2half2_rn(dz * r * gg.z + bb.z, dw * r * gg.w + bb.w);
}

// -------- fused selection + window gather (fp16 in/out) --------
__global__ void gather_kernel(const __half* __restrict__ h16,
                              const float* __restrict__ logits,
                              const float* __restrict__ gu,
                              __half* __restrict__ kv) {
    __shared__ int   s_start;
    __shared__ float s_scale;

    const int row = blockIdx.x;          // b*640 + s*128 + w
    const int b = row / (SSEL * WWIN);
    const int r = row % (SSEL * WWIN);
    const int s = r / WWIN;
    const int w = r % WWIN;
    const int sb = s * BB + b;
    const int t = threadIdx.x;           // 256

    if (t < 32) {
        const int lane = t;
        float u0 = gu[sb * NB + lane];
        float u1 = gu[sb * NB + 32 + lane];
        float g0 = -logf(-logf(u0 + 1e-9f) + 1e-9f);
        float g1 = -logf(-logf(u1 + 1e-9f) + 1e-9f);
        float p0 = logits[b * NB + lane] + g0;       // TAU = 1, b_sal shift dropped
        float p1 = logits[b * NB + 32 + lane] + g1;

        float m = p0; int idx = lane;
        if (p1 > m) { m = p1; idx = lane + 32; }
        #pragma unroll
        for (int o = 16; o; o >>= 1) {
            float om = __shfl_down_sync(0xffffffffu, m, o);
            int   oi = __shfl_down_sync(0xffffffffu, idx, o);
            if (om > m || (om == m && oi < idx)) { m = om; idx = oi; }
        }
        m   = __shfl_sync(0xffffffffu, m, 0);
        idx = __shfl_sync(0xffffffffu, idx, 0);

        float se = expf(p0 - m) + expf(p1 - m);
        #pragma unroll
        for (int o = 16; o; o >>= 1) se += __shfl_down_sync(0xffffffffu, se, o);
        if (lane == 0) {
            float ww = 1.0f / se;
            float scale = (1.0f + ww) - ww;
            int start = idx * BKBLK + BKBLK / 2 - WWIN / 2;
            if (start < 0) start = 0;
            if (start > LL - WWIN) start = LL - WWIN;
            s_start = start;
            s_scale = scale;
        }
    }
    __syncthreads();

    const int src = b * LL + s_start + w;
    const __half2 sc2 = __float2half2_rn(s_scale);
    uint2 raw = *reinterpret_cast<const uint2*>(h16 + (size_t)src * DD + t * 4);
    __half2* hp = reinterpret_cast<__half2*>(&raw);
    hp[0] = __hmul2(hp[0], sc2);
    hp[1] = __hmul2(hp[1], sc2);
    *reinterpret_cast<uint2*>(kv + (size_t)row * DD + t * 4) = raw;
}

// ===== FP16 tensor-core GEMM: 4-stage cp.async pipeline, dynamic smem ======
#define HA_STRIDE 40     // halfs
#define HB_NN_STRIDE 136 // halfs
#define HSTG 5120        // halfs per tile stage
#define NSTAGE 4
#define GEMM_SMEM (NSTAGE * 2 * HSTG * 2)   // 81920 bytes

template<bool BT, bool GELU, bool RES, bool OUTH>
__global__ __launch_bounds__(256, 2)
void hgemm(const __half* __restrict__ A,
           const __half* __restrict__ B,
           const float* __restrict__ bias,
           const float* __restrict__ res,
           void* __restrict__ Cout,
           int M, int N, int K) {
    extern __shared__ __half gsm[];
    const uint32_t sm_u32 = (uint32_t)__cvta_generic_to_shared(gsm);

    const int tid  = threadIdx.x;
    const int lane = tid & 31;
    const int wid  = tid >> 5;
    const int wm = (wid & 1) * 64;
    const int wn = (wid >> 1) * 32;
    const int lm = lane >> 2;
    const int lk = lane & 3;
    const int m0 = blockIdx.y * 128;
    const int n0 = blockIdx.x * 128;

    float acc[4][4][4];
    #pragma unroll
    for (int i = 0; i < 4; i++)
        #pragma unroll
        for (int j = 0; j < 4; j++)
            #pragma unroll
            for (int f = 0; f < 4; f++) acc[i][j][f] = 0.0f;

    auto issue = [&](int k0, int st) {
        __half* As = gsm + (size_t)st * HSTG;
        __half* Bs = gsm + (size_t)(NSTAGE + st) * HSTG;
        #pragma unroll
        for (int j = 0; j < 2; j++) {
            int idx = tid + j * 256;
            int r = idx >> 2, c = (idx & 3) * 8;
            cp16(&As[r * HA_STRIDE + c], A + (size_t)(m0 + r) * K + k0 + c);
        }
        #pragma unroll
        for (int j = 0; j < 2; j++) {
            int idx = tid + j * 256;
            if (BT) {
                int r = idx >> 2, c = (idx & 3) * 8;
                cp16(&Bs[r * HA_STRIDE + c], B + (size_t)(n0 + r) * K + k0 + c);
            } else {
                int r = idx >> 4, c = (idx & 15) * 8;
                cp16(&Bs[r * HB_NN_STRIDE + c], B + (size_t)(k0 + r) * N + n0 + c);
            }
        }
        cp_commit();
    };

    const int T = K >> 5;
    issue(0, 0);
    issue(32, 1);
    issue(64, 2);

    const int a_row  = lane & 15;
    const int a_colh = ((lane >> 4) << 3);
    const int g  = lane >> 3;
    const int lr = lane & 7;
    const int t_krow = ((g >> 1) << 3) + lr;
    const int t_ncol = (g & 1) << 3;

    for (int t = 0; t < T; t++) {
        const int buf = t & 3;
        if (t + 3 <= T) cp_wait2();
        else if (t + 2 == T) cp_wait1();
        else cp_wait0();
        __syncthreads();
        if (t + 3 < T) issue((t + 3) << 5, (t + 3) & 3);

        const uint32_t Au = sm_u32 + 2u * (uint32_t)(buf * HSTG);
        const uint32_t Bu = sm_u32 + 2u * (uint32_t)((NSTAGE + buf) * HSTG);

        #pragma unroll
        for (int ks = 0; ks < 2; ks++) {
            uint32_t a[4][4];
            #pragma unroll
            for (int mi = 0; mi < 4; mi++) {
                uint32_t addr = Au + 2 * ((wm + mi * 16 + a_row) * HA_STRIDE + ks * 16 + a_colh);
                ldsm4(a[mi][0], a[mi][1], a[mi][2], a[mi][3], addr);
            }
            uint32_t b[4][2];
            #pragma unroll
            for (int p = 0; p < 2; p++) {
                uint32_t r0, r1, r2, r3;
                if (BT) {
                    uint32_t addr = Bu + 2 * ((wn + p * 16 + a_row) * HA_STRIDE + ks * 16 + a_colh);
                    ldsm4(r0, r1, r2, r3, addr);
                } else {
                    uint32_t addr = Bu + 2 * ((ks * 16 + t_krow) * HB_NN_STRIDE + wn + p * 16 + t_ncol);
                    ldsm4t(r0, r1, r2, r3, addr);
                }
                b[p * 2 + 0][0] = r0; b[p * 2 + 0][1] = r2;
                b[p * 2 + 1][0] = r1; b[p * 2 + 1][1] = r3;
            }
            #pragma unroll
            for (int mi = 0; mi < 4; mi++)
                #pragma unroll
                for (int ni = 0; ni < 4; ni++)
                    mma_f16(acc[mi][ni], a[mi], b[ni]);
        }
    }

    #pragma unroll
    for (int ni = 0; ni < 4; ni++) {
        const int cn = n0 + wn + ni * 8 + lk * 2;
        const float bx = bias[cn], by = bias[cn + 1];
        #pragma unroll
        for (int mi = 0; mi < 4; mi++) {
            const int rm = m0 + wm + mi * 16 + lm;
            float v0 = acc[mi][ni][0] + bx;
            float v1 = acc[mi][ni][1] + by;
            float v2 = acc[mi][ni][2] + bx;
            float v3 = acc[mi][ni][3] + by;
            if (GELU) {
                float vv[4] = {v0, v1, v2, v3};
                #pragma unroll
                for (int j = 0; j < 4; j++) {
                    float v = vv[j];
                    float u = 0.7978845608028654f * (v + 0.044715f * v * v * v);
                    vv[j] = 0.5f * v * (1.0f + tanhf(u));
                }
                v0 = vv[0]; v1 = vv[1]; v2 = vv[2]; v3 = vv[3];
            }
            if (RES) {
                const float* rf = (const float*)res;
                float2 r0 = *reinterpret_cast<const float2*>(rf + (size_t)rm * N + cn);
                float2 r1 = *reinterpret_cast<const float2*>(rf + (size_t)(rm + 8) * N + cn);
                v0 += r0.x; v1 += r0.y; v2 += r1.x; v3 += r1.y;
            }
            if (OUTH) {
                __half* C = (__half*)Cout;
                *reinterpret_cast<__half2*>(C + (size_t)rm * N + cn) = __floats2half2_rn(v0, v1);
                *reinterpret_cast<__half2*>(C + (size_t)(rm + 8) * N + cn) = __floats2half2_rn(v2, v3);
            } else {
                float* C = (float*)Cout;
                float2 o0 = {v0, v1}, o1 = {v2, v3};
                *reinterpret_cast<float2*>(C + (size_t)rm * N + cn) = o0;
                *reinterpret_cast<float2*>(C + (size_t)(rm + 8) * N + cn) = o1;
            }
        }
    }
}

// ====== fused QKV GEMM (NT, fp16 out), 4-stage pipeline =====================
__global__ __launch_bounds__(256, 2)
void hgemm_qkv(const __half* __restrict__ h16,
               const __half* __restrict__ kv16,
               const __half* __restrict__ ipw16,
               const float* __restrict__ ipb,
               __half* __restrict__ qo,
               __half* __restrict__ ko,
               __half* __restrict__ vo) {
    extern __shared__ __half gsm[];
    const uint32_t sm_u32 = (uint32_t)__cvta_generic_to_shared(gsm);

    const int y = blockIdx.y;
    int seg, my;
    if (y < 64)      { seg = 0; my = y; }
    else if (y < 84) { seg = 1; my = y - 64; }
    else             { seg = 2; my = y - 84; }
    const __half* A = (seg == 0) ? h16 : kv16;
    const __half* B = ipw16 + (size_t)seg * DD * DD;
    const float* bias = ipb + seg * DD;
    __half* C = (seg == 0) ? qo : ((seg == 1) ? ko : vo);
    const int K = DD, N = DD;
    const int m0 = my * 128;
    const int n0 = blockIdx.x * 128;

    const int tid  = threadIdx.x;
    const int lane = tid & 31;
    const int wid  = tid >> 5;
    const int wm = (wid & 1) * 64;
    const int wn = (wid >> 1) * 32;
    const int lm = lane >> 2;
    const int lk = lane & 3;

    float acc[4][4][4];
    #pragma unroll
    for (int i = 0; i < 4; i++)
        #pragma unroll
        for (int j = 0; j < 4; j++)
            #pragma unroll
            for (int f = 0; f < 4; f++) acc[i][j][f] = 0.0f;

    auto issue = [&](int k0, int st) {
        __half* As = gsm + (size_t)st * HSTG;
        __half* Bs = gsm + (size_t)(NSTAGE + st) * HSTG;
        #pragma unroll
        for (int j = 0; j < 2; j++) {
            int idx = tid + j * 256;
            int r = idx >> 2, c = (idx & 3) * 8;
            cp16(&As[r * HA_STRIDE + c], A + (size_t)(m0 + r) * K + k0 + c);
        }
        #pragma unroll
        for (int j = 0; j < 2; j++) {
            int idx = tid + j * 256;
            int r = idx >> 2, c = (idx & 3) * 8;
            cp16(&Bs[r * HA_STRIDE + c], B + (size_t)(n0 + r) * K + k0 + c);
        }
        cp_commit();
    };

    const int T = K >> 5;
    issue(0, 0);
    issue(32, 1);
    issue(64, 2);

    const int a_row  = lane & 15;
    const int a_colh = ((lane >> 4) << 3);

    for (int t = 0; t < T; t++) {
        const int buf = t & 3;
        if (t + 3 <= T) cp_wait2();
        else if (t + 2 == T) cp_wait1();
        else cp_wait0();
        __syncthreads();
        if (t + 3 < T) issue((t + 3) << 5, (t + 3) & 3);

        const uint32_t Au = sm_u32 + 2u * (uint32_t)(buf * HSTG);
        const uint32_t Bu = sm_u32 + 2u * (uint32_t)((NSTAGE + buf) * HSTG);

        #pragma unroll
        for (int ks = 0; ks < 2; ks++) {
            uint32_t a[4][4];
            #pragma unroll
            for (int mi = 0; mi < 4; mi++) {
                uint32_t addr = Au + 2 * ((wm + mi * 16 + a_row) * HA_STRIDE + ks * 16 + a_colh);
                ldsm4(a[mi][0], a[mi][1], a[mi][2], a[mi][3], addr);
            }
            uint32_t b[4][2];
            #pragma unroll
            for (int p = 0; p < 2; p++) {
                uint32_t r0, r1, r2, r3;
                uint32_t addr = Bu + 2 * ((wn + p * 16 + a_row) * HA_STRIDE + ks * 16 + a_colh);
                ldsm4(r0, r1, r2, r3, addr);
                b[p * 2 + 0][0] = r0; b[p * 2 + 0][1] = r2;
                b[p * 2 + 1][0] = r1; b[p * 2 + 1][1] = r3;
            }
            #pragma unroll
            for (int mi = 0; mi < 4; mi++)
                #pragma unroll
                for (int ni = 0; ni < 4; ni++)
                    mma_f16(acc[mi][ni], a[mi], b[ni]);
        }
    }

    #pragma unroll
    for (int ni = 0; ni < 4; ni++) {
        const int cn = n0 + wn + ni * 8 + lk * 2;
        const float bx = bias[cn], by = bias[cn + 1];
        #pragma unroll
        for (int mi = 0; mi < 4; mi++) {
            const int rm = m0 + wm + mi * 16 + lm;
            *reinterpret_cast<__half2*>(C + (size_t)rm * N + cn) =
                __floats2half2_rn(acc[mi][ni][0] + bx, acc[mi][ni][1] + by);
            *reinterpret_cast<__half2*>(C + (size_t)(rm + 8) * N + cn) =
                __floats2half2_rn(acc[mi][ni][2] + bx, acc[mi][ni][3] + by);
        }
    }
}

// ====== flash attention: fp16 mma, 128 q/block, V via ldsm4t (no vtrans) ====
#define FA_STR 72   // halfs per smem row (64 + 8 pad); row pitch 144B
#define FA_Q_OFF 0
#define FA_K_OFF (128 * FA_STR)
#define FA_V_OFF (192 * FA_STR)
#define FA_P_OFF (256 * FA_STR)
#define FA_SMEM_HALFS (384 * FA_STR)

__global__ __launch_bounds__(256)
void fattn16_kernel(const __half* __restrict__ q,
                    const __half* __restrict__ k,
                    const __half* __restrict__ v,
                    __half* __restrict__ o) {
    extern __shared__ __half fsm[];
    __half* Qh = fsm + FA_Q_OFF;
    __half* Kh = fsm + FA_K_OFF;
    __half* Vh = fsm + FA_V_OFF;   // natural [j][d] layout
    __half* Ph = fsm + FA_P_OFF;
    const uint32_t base_u = (uint32_t)__cvta_generic_to_shared(fsm);
    const uint32_t Qu = base_u + 2 * FA_Q_OFF;
    const uint32_t Ku = base_u + 2 * FA_K_OFF;
    const uint32_t Vu = base_u + 2 * FA_V_OFF;
    const uint32_t Pu = base_u + 2 * FA_P_OFF;

    const int bh = blockIdx.y;
    const int b = bh >> 4, hh = bh & 15;
    const int q0 = blockIdx.x * 128;
    const int tid = threadIdx.x, lane = tid & 31, wid = tid >> 5;
    const int lm = lane >> 2, lk = lane & 3;
    const int wm = wid * 16;   // 8 warps -> 128 query rows

    const int a_row  = lane & 15;
    const int a_colh = ((lane >> 4) << 3);
    const int g  = lane >> 3;
    const int lr = lane & 7;
    const int t_krow = ((g >> 1) << 3) + lr;
    const int t_ncol = (g & 1) << 3;

    // load Q tile: 128 rows (scaled by 1/8, exact in fp16)
    {
        const __half2 sc = __floats2half2_rn(0.125f, 0.125f);
        const __half* qg = q + ((size_t)(b * LL + q0)) * DD + hh * DH;
        #pragma unroll
        for (int it = 0; it < 4; it++) {
            int idx = tid + it * 256;          // 0..1023
            int r = idx >> 3, c = (idx & 7) * 8;
            uint4 raw = *reinterpret_cast<const uint4*>(qg + (size_t)r * DD + c);
            __half2* hp = reinterpret_cast<__half2*>(&raw);
            hp[0] = __hmul2(hp[0], sc); hp[1] = __hmul2(hp[1], sc);
            hp[2] = __hmul2(hp[2], sc); hp[3] = __hmul2(hp[3], sc);
            *reinterpret_cast<uint4*>(&Qh[r * FA_STR + c]) = raw;
        }
    }

    float mrow0 = -1e30f, mrow1 = -1e30f, lrow0 = 0.0f, lrow1 = 0.0f;
    float oacc[8][4];
    #pragma unroll
    for (int ni = 0; ni < 8; ni++)
        #pragma unroll
        for (int f = 0; f < 4; f++) oacc[ni][f] = 0.0f;

    const __half* kg = k + ((size_t)(b * NKEY)) * DD + hh * DH;
    const __half* vg = v + ((size_t)(b * NKEY)) * DD + hh * DH;

    for (int kt = 0; kt < NKEY / 64; kt++) {
        __syncthreads();
        #pragma unroll
        for (int it = 0; it < 2; it++) {
            int idx = tid + it * 256;
            int r = idx >> 3, c = (idx & 7) * 8;
            *reinterpret_cast<uint4*>(&Kh[r * FA_STR + c]) =
                *reinterpret_cast<const uint4*>(kg + (size_t)(kt * 64 + r) * DD + c);
            *reinterpret_cast<uint4*>(&Vh[r * FA_STR + c]) =
                *reinterpret_cast<const uint4*>(vg + (size_t)(kt * 64 + r) * DD + c);
        }
        __syncthreads();

        // S = Q @ K^T (fp16 mma)
        float s[8][4];
        #pragma unroll
        for (int ni = 0; ni < 8; ni++)
            #pragma unroll
            for (int f = 0; f < 4; f++) s[ni][f] = 0.0f;

        #pragma unroll
        for (int kk = 0; kk < 4; kk++) {
            uint32_t a[4];
            ldsm4(a[0], a[1], a[2], a[3],
                  Qu + 2 * ((wm + a_row) * FA_STR + kk * 16 + a_colh));
            #pragma unroll
            for (int p = 0; p < 4; p++) {
                uint32_t r0, r1, r2, r3;
                ldsm4(r0, r1, r2, r3,
                      Ku + 2 * ((p * 16 + a_row) * FA_STR + kk * 16 + a_colh));
                uint32_t b0[2] = {r0, r2}, b1[2] = {r1, r3};
                mma_f16(s[p * 2 + 0], a, b0);
                mma_f16(s[p * 2 + 1], a, b1);
            }
        }

        // online softmax (rows lm, lm+8)
        float rm0 = -1e30f, rm1 = -1e30f;
        #pragma unroll
        for (int ni = 0; ni < 8; ni++) {
            rm0 = fmaxf(rm0, fmaxf(s[ni][0], s[ni][1]));
            rm1 = fmaxf(rm1, fmaxf(s[ni][2], s[ni][3]));
        }
        rm0 = fmaxf(rm0, __shfl_xor_sync(0xffffffffu, rm0, 1));
        rm0 = fmaxf(rm0, __shfl_xor_sync(0xffffffffu, rm0, 2));
        rm1 = fmaxf(rm1, __shfl_xor_sync(0xffffffffu, rm1, 1));
        rm1 = fmaxf(rm1, __shfl_xor_sync(0xffffffffu, rm1, 2));

        float nm0 = fmaxf(mrow0, rm0), nm1 = fmaxf(mrow1, rm1);
        float al0 = __expf(mrow0 - nm0), al1 = __expf(mrow1 - nm1);
        mrow0 = nm0; mrow1 = nm1;

        float rs0 = 0.0f, rs1 = 0.0f;
        #pragma unroll
        for (int ni = 0; ni < 8; ni++) {
            s[ni][0] = __expf(s[ni][0] - nm0);
            s[ni][1] = __expf(s[ni][1] - nm0);
            s[ni][2] = __expf(s[ni][2] - nm1);
            s[ni][3] = __expf(s[ni][3] - nm1);
            rs0 += s[ni][0] + s[ni][1];
            rs1 += s[ni][2] + s[ni][3];
        }
        rs0 += __shfl_xor_sync(0xffffffffu, rs0, 1);
        rs0 += __shfl_xor_sync(0xffffffffu, rs0, 2);
        rs1 += __shfl_xor_sync(0xffffffffu, rs1, 1);
        rs1 += __shfl_xor_sync(0xffffffffu, rs1, 2);

        lrow0 = lrow0 * al0 + rs0;
        lrow1 = lrow1 * al1 + rs1;

        #pragma unroll
        for (int ni = 0; ni < 8; ni++) {
            oacc[ni][0] *= al0; oacc[ni][1] *= al0;
            oacc[ni][2] *= al1; oacc[ni][3] *= al1;
        }

        // P -> smem fp16 (own warp rows only)
        #pragma unroll
        for (int ni = 0; ni < 8; ni++) {
            __half* pp = &Ph[(wm + lm) * FA_STR + ni * 8 + 2 * lk];
            *reinterpret_cast<__half2*>(pp) = __floats2half2_rn(s[ni][0], s[ni][1]);
            *reinterpret_cast<__half2*>(pp + 8 * FA_STR) = __floats2half2_rn(s[ni][2], s[ni][3]);
        }
        __syncwarp();

        // O += P @ V : Vh is [j][d] = [K][N] row-major -> ldsm4t (hgemm NN idiom)
        #pragma unroll
        for (int kk = 0; kk < 4; kk++) {
            uint32_t a[4];
            ldsm4(a[0], a[1], a[2], a[3],
                  Pu + 2 * ((wm + a_row) * FA_STR + kk * 16 + a_colh));
            #pragma unroll
            for (int p = 0; p < 4; p++) {
                uint32_t r0, r1, r2, r3;
                ldsm4t(r0, r1, r2, r3,
                       Vu + 2 * ((kk * 16 + t_krow) * FA_STR + p * 16 + t_ncol));
                uint32_t b0[2] = {r0, r2}, b1[2] = {r1, r3};
                mma_f16(oacc[p * 2 + 0], a, b0);
                mma_f16(oacc[p * 2 + 1], a, b1);
            }
        }
    }

    const float inv0 = 1.0f / lrow0, inv1 = 1.0f / lrow1;
    __half* og = o + ((size_t)(b * LL + q0 + wm + lm)) * DD + hh * DH;
    #pragma unroll
    for (int ni = 0; ni < 8; ni++) {
        const int cc = ni * 8 + 2 * lk;
        *reinterpret_cast<__half2*>(og + cc) =
            __floats2half2_rn(oacc[ni][0] * inv0, oacc[ni][1] * inv0);
        *reinterpret_cast<__half2*>(og + (size_t)8 * DD + cc) =
            __floats2half2_rn(oacc[ni][2] * inv1, oacc[ni][3] * inv1);
    }
}

// ---------------- driver ----------------
extern "C" void kernel_launch(void* const* d_in, const int* in_sizes, int n_in,
                              void* d_out, int out_size) {
    const float* x        = (const float*)d_in[0];
    const float* gumbel_u = (const float*)d_in[1];
    const float* ln1_g    = (const float*)d_in[2];
    const float* ln1_b    = (const float*)d_in[3];
    const float* ln2_g    = (const float*)d_in[4];
    const float* ln2_b    = (const float*)d_in[5];
    const float* w_sal    = (const float*)d_in[6];
    const float* b_sal    = (const float*)d_in[7];   // constant shift: cancels, unused
    const float* ipw      = (const float*)d_in[8];
    const float* ipb      = (const float*)d_in[9];
    const float* opw      = (const float*)d_in[10];
    const float* opb      = (const float*)d_in[11];
    const float* w_fc     = (const float*)d_in[12];
    const float* b_fc     = (const float*)d_in[13];
    const float* w_proj   = (const float*)d_in[14];
    const float* b_proj   = (const float*)d_in[15];
    float* out = (float*)d_out;
    (void)b_sal;

    void* p;
    cudaGetSymbolAddress(&p, g_h16);    __half* h16   = (__half*)p;
    cudaGetSymbolAddress(&p, g_kv16);   __half* kv16  = (__half*)p;
    cudaGetSymbolAddress(&p, g_q16);    __half* q16   = (__half*)p;
    cudaGetSymbolAddress(&p, g_k16);    __half* k16   = (__half*)p;
    cudaGetSymbolAddress(&p, g_v16);    __half* v16   = (__half*)p;
    cudaGetSymbolAddress(&p, g_att16);  __half* att16 = (__half*)p;
    cudaGetSymbolAddress(&p, g_x2);     float*  x2    = (float*)p;
    cudaGetSymbolAddress(&p, g_h2_16);  __half* h2_16 = (__half*)p;
    cudaGetSymbolAddress(&p, g_ff16);   __half* ff16  = (__half*)p;
    cudaGetSymbolAddress(&p, g_w16);    __half* w16   = (__half*)p;
    cudaGetSymbolAddress(&p, g_logits); float*  logi  = (float*)p;

    const int FA_SMEM = FA_SMEM_HALFS * 2;   // 55296 bytes
    cudaFuncSetAttribute(fattn16_kernel, cudaFuncAttributeMaxDynamicSharedMemorySize, FA_SMEM);
    cudaFuncSetAttribute(hgemm<true,  false, true,  false>, cudaFuncAttributeMaxDynamicSharedMemorySize, GEMM_SMEM);
    cudaFuncSetAttribute(hgemm<false, true,  false, true >, cudaFuncAttributeMaxDynamicSharedMemorySize, GEMM_SMEM);
    cudaFuncSetAttribute(hgemm<false, false, true,  false>, cudaFuncAttributeMaxDynamicSharedMemorySize, GEMM_SMEM);
    cudaFuncSetAttribute(hgemm_qkv, cudaFuncAttributeMaxDynamicSharedMemorySize, GEMM_SMEM);

    // 0. weight prep + logits zeroing
    f2h_all_kernel<<<(W16_TOTAL / 4 + 255) / 256, 256>>>(ipw, opw, w_fc, w_proj, w16);
    cudaMemsetAsync(logi, 0, BB * NB * sizeof(float));
    // 1. LN1 + fused saliency logits (fp16 h out, atomic logits)
    ln1_sal_kernel<<<NTOK, 256>>>(x, ln1_g, ln1_b, w_sal, h16, logi);
    // 2+3. fused selection + gather -> kv16 (reads fp16 h)
    gather_kernel<<<MKV, 256>>>(h16, logi, gumbel_u, kv16);
    // 4. fused QKV projection (fp16 out, 4-stage pipeline)
    hgemm_qkv<<<dim3(DD / 128, 64 + 20 + 20), 256, GEMM_SMEM>>>(
        h16, kv16, w16 + W16_IPW, ipb, q16, k16, v16);
    // 5. attention (fp16 mma flash, V transposed in-kernel via ldsm4t)
    fattn16_kernel<<<dim3(LL / 128, BB * NH), 256, FA_SMEM>>>(q16, k16, v16, att16);
    // 6. out proj + residual (fp32 out)
    hgemm<true, false, true, false><<<dim3(DD / 128, NTOK / 128), 256, GEMM_SMEM>>>(
        att16, w16 + W16_OPW, opb, x, x2, NTOK, DD, DD);
    // 7. LN2 (fp16 out)
    ln2_kernel<<<NTOK, 256>>>(x2, ln2_g, ln2_b, h2_16);
    // 8. FFN up + gelu (NN, fp16 out)
    hgemm<false, true, false, true><<<dim3(DFFN / 128, NTOK / 128), 256, GEMM_SMEM>>>(
        h2_16, w16 + W16_WFC, b_fc, nullptr, ff16, NTOK, DFFN, DD);
    // 9. FFN down + residual (NN, fp32 out) -> out
    hgemm<false, false, true, false><<<dim3(DD / 128, NTOK / 128), 256, GEMM_SMEM>>>(
        ff16, w16 + W16_WPROJ, b_proj, x2, out, NTOK, DD, DFFN);
}

// round 15
// speedup vs baseline: 1.0319x; 1.0319x over previous
#include <cuda_runtime.h>
#include <cuda_fp16.h>
#include <math.h>
#include <stdint.h>

// ---------------- problem constants ----------------
#define DD     1024
#define LL     2048
#define BB     4
#define NH     16
#define DH     64
#define SSEL   5
#define WWIN   128
#define BKBLK  32
#define NB     64          // L / BK
#define NTOK   8192        // B*L
#define MKV    2560        // B*S*W
#define NKEY   640         // S*W keys per batch
#define DFFN   4096

// ---------------- scratch (device globals; no allocations allowed) --------
__device__ __half g_h16 [NTOK * DD];
__device__ __half g_kv16[MKV  * DD];
__device__ __half g_q16 [NTOK * DD];
__device__ __half g_k16 [MKV  * DD];
__device__ __half g_v16 [MKV  * DD];
__device__ __half g_att16[NTOK * DD];
__device__ float  g_x2  [NTOK * DD];
__device__ __half g_h2_16[NTOK * DD];
__device__ __half g_ff16 [NTOK * DFFN];
__device__ __half g_w16  [12582912];     // fp16 weights: ipw | opw | w_fc | w_proj
__device__ float  g_logits[BB * NB];

#define W16_IPW   0
#define W16_OPW   3145728
#define W16_WFC   4194304
#define W16_WPROJ 8388608
#define W16_TOTAL 12582912

// ---------------- helpers ----------------
__device__ __forceinline__ void mma_f16(float* d, const uint32_t* a, const uint32_t* b) {
    asm volatile(
        "mma.sync.aligned.m16n8k16.row.col.f32.f16.f16.f32 "
        "{%0,%1,%2,%3}, {%4,%5,%6,%7}, {%8,%9}, {%0,%1,%2,%3};\n"
        : "+f"(d[0]), "+f"(d[1]), "+f"(d[2]), "+f"(d[3])
        : "r"(a[0]), "r"(a[1]), "r"(a[2]), "r"(a[3]), "r"(b[0]), "r"(b[1]));
}

__device__ __forceinline__ void ldsm4(uint32_t& r0, uint32_t& r1, uint32_t& r2, uint32_t& r3,
                                      uint32_t addr) {
    asm volatile("ldmatrix.sync.aligned.m8n8.x4.shared.b16 {%0,%1,%2,%3}, [%4];"
                 : "=r"(r0), "=r"(r1), "=r"(r2), "=r"(r3) : "r"(addr));
}
__device__ __forceinline__ void ldsm4t(uint32_t& r0, uint32_t& r1, uint32_t& r2, uint32_t& r3,
                                       uint32_t addr) {
    asm volatile("ldmatrix.sync.aligned.m8n8.x4.trans.shared.b16 {%0,%1,%2,%3}, [%4];"
                 : "=r"(r0), "=r"(r1), "=r"(r2), "=r"(r3) : "r"(addr));
}

__device__ __forceinline__ void cp16(void* s, const void* g) {
    unsigned sa = (unsigned)__cvta_generic_to_shared(s);
    asm volatile("cp.async.cg.shared.global [%0], [%1], 16;\n" :: "r"(sa), "l"(g));
}
__device__ __forceinline__ void cp_commit() { asm volatile("cp.async.commit_group;\n"); }
__device__ __forceinline__ void cp_wait0()  { asm volatile("cp.async.wait_group 0;\n"); }

// ---------------- fused fp32 -> fp16 weight conversion ----------------
__global__ void f2h_all_kernel(const float* __restrict__ ipw,
                               const float* __restrict__ opw,
                               const float* __restrict__ wfc,
                               const float* __restrict__ wproj,
                               __half* __restrict__ w16) {
    int i = (blockIdx.x * blockDim.x + threadIdx.x) * 4;
    if (i >= W16_TOTAL) return;
    const float* src;
    if (i < W16_OPW)        src = ipw + i;
    else if (i < W16_WFC)   src = opw + (i - W16_OPW);
    else if (i < W16_WPROJ) src = wfc + (i - W16_WFC);
    else                    src = wproj + (i - W16_WPROJ);
    float4 v = *reinterpret_cast<const float4*>(src);
    __half2* d = reinterpret_cast<__half2*>(w16 + i);
    d[0] = __floats2half2_rn(v.x, v.y);
    d[1] = __floats2half2_rn(v.z, v.w);
}

// ---------- LN1 + fused saliency: one block per token ----------
__global__ void ln1_sal_kernel(const float* __restrict__ x,
                               const float* __restrict__ gam,
                               const float* __restrict__ bet,
                               const float* __restrict__ w_sal,
                               __half* __restrict__ out16,
                               float* __restrict__ logits) {
    __shared__ float red[8];
    const int row = blockIdx.x;
    const int t = threadIdx.x;  // 256
    const float4* xr = reinterpret_cast<const float4*>(x) + (size_t)row * (DD / 4);
    float4 v = xr[t];

    float s = v.x + v.y + v.z + v.w;
    #pragma unroll
    for (int o = 16; o; o >>= 1) s += __shfl_down_sync(0xffffffffu, s, o);
    if ((t & 31) == 0) red[t >> 5] = s;
    __syncthreads();
    float tot = red[0] + red[1] + red[2] + red[3] + red[4] + red[5] + red[6] + red[7];
    const float mean = tot * (1.0f / DD);
    __syncthreads();

    float dx = v.x - mean, dy = v.y - mean, dz = v.z - mean, dw = v.w - mean;
    float sq = dx * dx + dy * dy + dz * dz + dw * dw;
    #pragma unroll
    for (int o = 16; o; o >>= 1) sq += __shfl_down_sync(0xffffffffu, sq, o);
    if ((t & 31) == 0) red[t >> 5] = sq;
    __syncthreads();
    float var = (red[0] + red[1] + red[2] + red[3] + red[4] + red[5] + red[6] + red[7]) * (1.0f / DD);
    const float r = rsqrtf(var + 1e-5f);

    const float4 gg = reinterpret_cast<const float4*>(gam)[t];
    const float4 bb = reinterpret_cast<const float4*>(bet)[t];
    float4 o4;
    o4.x = dx * r * gg.x + bb.x;
    o4.y = dy * r * gg.y + bb.y;
    o4.z = dz * r * gg.z + bb.z;
    o4.w = dw * r * gg.w + bb.w;
    __half2* d = reinterpret_cast<__half2*>(out16 + (size_t)row * DD + t * 4);
    d[0] = __floats2half2_rn(o4.x, o4.y);
    d[1] = __floats2half2_rn(o4.z, o4.w);

    const float4 ws = reinterpret_cast<const float4*>(w_sal)[t];
    float dsal = o4.x * ws.x + o4.y * ws.y + o4.z * ws.z + o4.w * ws.w;
    __syncthreads();
    #pragma unroll
    for (int o = 16; o; o >>= 1) dsal += __shfl_down_sync(0xffffffffu, dsal, o);
    if ((t & 31) == 0) red[t >> 5] = dsal;
    __syncthreads();
    if (t == 0) {
        float dtot = red[0] + red[1] + red[2] + red[3] + red[4] + red[5] + red[6] + red[7];
        atomicAdd(&logits[row >> 5], dtot * (1.0f / BKBLK));
    }
}

// ---------------- LayerNorm (LN2): one block per token, fp16 out ----------
__global__ void ln2_kernel(const float* __restrict__ x,
                           const float* __restrict__ gam,
                           const float* __restrict__ bet,
                           __half* __restrict__ out16) {
    __shared__ float red[8];
    const int row = blockIdx.x;
    const int t = threadIdx.x;  // 256
    const float4* xr = reinterpret_cast<const float4*>(x) + (size_t)row * (DD / 4);
    float4 v = xr[t];

    float s = v.x + v.y + v.z + v.w;
    #pragma unroll
    for (int o = 16; o; o >>= 1) s += __shfl_down_sync(0xffffffffu, s, o);
    if ((t & 31) == 0) red[t >> 5] = s;
    __syncthreads();
    float tot = red[0] + red[1] + red[2] + red[3] + red[4] + red[5] + red[6] + red[7];
    const float mean = tot * (1.0f / DD);
    __syncthreads();

    float dx = v.x - mean, dy = v.y - mean, dz = v.z - mean, dw = v.w - mean;
    float sq = dx * dx + dy * dy + dz * dz + dw * dw;
    #pragma unroll
    for (int o = 16; o; o >>= 1) sq += __shfl_down_sync(0xffffffffu, sq, o);
    if ((t & 31) == 0) red[t >> 5] = sq;
    __syncthreads();
    float var = (red[0] + red[1] + red[2] + red[3] + red[4] + red[5] + red[6] + red[7]) * (1.0f / DD);
    const float r = rsqrtf(var + 1e-5f);

    const float4 gg = reinterpret_cast<const float4*>(gam)[t];
    const float4 bb = reinterpret_cast<const float4*>(bet)[t];
    __half2* d = reinterpret_cast<__half2*>(out16 + (size_t)row * DD + t * 4);
    d[0] = __floats2half2_rn(dx * r * gg.x + bb.x, dy * r * gg.y + bb.y);
    d[1] = __floats2half2_rn(dz * r * gg.z + bb.z, dw * r * gg.w + bb.w);
}

// -------- fused selection + window gather (fp16 in/out) --------
__global__ void gather_kernel(const __half* __restrict__ h16,
                              const float* __restrict__ logits,
                              const float* __restrict__ gu,
                              __half* __restrict__ kv) {
    __shared__ int   s_start;
    __shared__ float s_scale;

    const int row = blockIdx.x;          // b*640 + s*128 + w
    const int b = row / (SSEL * WWIN);
    const int r = row % (SSEL * WWIN);
    const int s = r / WWIN;
    const int w = r % WWIN;
    const int sb = s * BB + b;
    const int t = threadIdx.x;           // 256

    if (t < 32) {
        const int lane = t;
        float u0 = gu[sb * NB + lane];
        float u1 = gu[sb * NB + 32 + lane];
        float g0 = -logf(-logf(u0 + 1e-9f) + 1e-9f);
        float g1 = -logf(-logf(u1 + 1e-9f) + 1e-9f);
        float p0 = logits[b * NB + lane] + g0;       // TAU = 1, b_sal shift dropped
        float p1 = logits[b * NB + 32 + lane] + g1;

        float m = p0; int idx = lane;
        if (p1 > m) { m = p1; idx = lane + 32; }
        #pragma unroll
        for (int o = 16; o; o >>= 1) {
            float om = __shfl_down_sync(0xffffffffu, m, o);
            int   oi = __shfl_down_sync(0xffffffffu, idx, o);
            if (om > m || (om == m && oi < idx)) { m = om; idx = oi; }
        }
        m   = __shfl_sync(0xffffffffu, m, 0);
        idx = __shfl_sync(0xffffffffu, idx, 0);

        float se = expf(p0 - m) + expf(p1 - m);
        #pragma unroll
        for (int o = 16; o; o >>= 1) se += __shfl_down_sync(0xffffffffu, se, o);
        if (lane == 0) {
            float ww = 1.0f / se;
            float scale = (1.0f + ww) - ww;
            int start = idx * BKBLK + BKBLK / 2 - WWIN / 2;
            if (start < 0) start = 0;
            if (start > LL - WWIN) start = LL - WWIN;
            s_start = start;
            s_scale = scale;
        }
    }
    __syncthreads();

    const int src = b * LL + s_start + w;
    const __half2 sc2 = __float2half2_rn(s_scale);
    uint2 raw = *reinterpret_cast<const uint2*>(h16 + (size_t)src * DD + t * 4);
    __half2* hp = reinterpret_cast<__half2*>(&raw);
    hp[0] = __hmul2(hp[0], sc2);
    hp[1] = __hmul2(hp[1], sc2);
    *reinterpret_cast<uint2*>(kv + (size_t)row * DD + t * 4) = raw;
}

// ===== FP16 tensor-core GEMM: 512 threads, warp tile 32x32, 2-stage ========
#define HA_STRIDE 40     // halfs
#define HB_NN_STRIDE 136 // halfs
#define HSTG 5120        // halfs per tile stage

template<bool BT, bool GELU, bool RES, bool OUTH>
__global__ __launch_bounds__(512, 2)
void hgemm(const __half* __restrict__ A,
           const __half* __restrict__ B,
           const float* __restrict__ bias,
           const float* __restrict__ res,
           void* __restrict__ Cout,
           int M, int N, int K) {
    __shared__ __half sm[4 * HSTG];
    const uint32_t sm_u32 = (uint32_t)__cvta_generic_to_shared(sm);
    __half* As = sm;
    __half* Bs = sm + 2 * HSTG;

    const int tid  = threadIdx.x;       // 512
    const int lane = tid & 31;
    const int wid  = tid >> 5;          // 0..15
    const int wm = (wid & 3) * 32;      // 4 warps along M
    const int wn = (wid >> 2) * 32;     // 4 warps along N
    const int lm = lane >> 2;
    const int lk = lane & 3;
    const int m0 = blockIdx.y * 128;
    const int n0 = blockIdx.x * 128;

    float acc[2][4][4];
    #pragma unroll
    for (int i = 0; i < 2; i++)
        #pragma unroll
        for (int j = 0; j < 4; j++)
            #pragma unroll
            for (int f = 0; f < 4; f++) acc[i][j][f] = 0.0f;

    auto issue = [&](int k0, int buf) {
        {
            int r = tid >> 2, c = (tid & 3) * 8;      // 512 granules exactly
            cp16(&As[buf * HSTG + r * HA_STRIDE + c],
                 A + (size_t)(m0 + r) * K + k0 + c);
        }
        if (BT) {
            int r = tid >> 2, c = (tid & 3) * 8;
            cp16(&Bs[buf * HSTG + r * HA_STRIDE + c],
                 B + (size_t)(n0 + r) * K + k0 + c);
        } else {
            int r = tid >> 4, c = (tid & 15) * 8;
            cp16(&Bs[buf * HSTG + r * HB_NN_STRIDE + c],
                 B + (size_t)(k0 + r) * N + n0 + c);
        }
    };

    issue(0, 0);
    cp_commit();
    cp_wait0();
    __syncthreads();

    const int a_row  = lane & 15;
    const int a_colh = ((lane >> 4) << 3);
    const int g  = lane >> 3;
    const int lr = lane & 7;
    const int t_krow = ((g >> 1) << 3) + lr;
    const int t_ncol = (g & 1) << 3;

    const int T = K >> 5;
    for (int t = 0; t < T; t++) {
        const int buf = t & 1;
        if (t + 1 < T) { issue((t + 1) << 5, buf ^ 1); cp_commit(); }

        const uint32_t Au = sm_u32 + 2u * (uint32_t)(buf * HSTG);
        const uint32_t Bu = sm_u32 + 2u * (uint32_t)((2 + buf) * HSTG);

        #pragma unroll
        for (int ks = 0; ks < 2; ks++) {
            uint32_t a[2][4];
            #pragma unroll
            for (int mi = 0; mi < 2; mi++) {
                uint32_t addr = Au + 2 * ((wm + mi * 16 + a_row) * HA_STRIDE + ks * 16 + a_colh);
                ldsm4(a[mi][0], a[mi][1], a[mi][2], a[mi][3], addr);
            }
            uint32_t b[4][2];
            #pragma unroll
            for (int p = 0; p < 2; p++) {
                uint32_t r0, r1, r2, r3;
                if (BT) {
                    uint32_t addr = Bu + 2 * ((wn + p * 16 + a_row) * HA_STRIDE + ks * 16 + a_colh);
                    ldsm4(r0, r1, r2, r3, addr);
                } else {
                    uint32_t addr = Bu + 2 * ((ks * 16 + t_krow) * HB_NN_STRIDE + wn + p * 16 + t_ncol);
                    ldsm4t(r0, r1, r2, r3, addr);
                }
                b[p * 2 + 0][0] = r0; b[p * 2 + 0][1] = r2;
                b[p * 2 + 1][0] = r1; b[p * 2 + 1][1] = r3;
            }
            #pragma unroll
            for (int mi = 0; mi < 2; mi++)
                #pragma unroll
                for (int ni = 0; ni < 4; ni++)
                    mma_f16(acc[mi][ni], a[mi], b[ni]);
        }

        if (t + 1 < T) { cp_wait0(); __syncthreads(); }
    }

    #pragma unroll
    for (int ni = 0; ni < 4; ni++) {
        const int cn = n0 + wn + ni * 8 + lk * 2;
        const float bx = bias[cn], by = bias[cn + 1];
        #pragma unroll
        for (int mi = 0; mi < 2; mi++) {
            const int rm = m0 + wm + mi * 16 + lm;
            float v0 = acc[mi][ni][0] + bx;
            float v1 = acc[mi][ni][1] + by;
            float v2 = acc[mi][ni][2] + bx;
            float v3 = acc[mi][ni][3] + by;
            if (GELU) {
                float vv[4] = {v0, v1, v2, v3};
                #pragma unroll
                for (int j = 0; j < 4; j++) {
                    float v = vv[j];
                    float u = 0.7978845608028654f * (v + 0.044715f * v * v * v);
                    vv[j] = 0.5f * v * (1.0f + tanhf(u));
                }
                v0 = vv[0]; v1 = vv[1]; v2 = vv[2]; v3 = vv[3];
            }
            if (RES) {
                const float* rf = (const float*)res;
                float2 r0 = *reinterpret_cast<const float2*>(rf + (size_t)rm * N + cn);
                float2 r1 = *reinterpret_cast<const float2*>(rf + (size_t)(rm + 8) * N + cn);
                v0 += r0.x; v1 += r0.y; v2 += r1.x; v3 += r1.y;
            }
            if (OUTH) {
                __half* C = (__half*)Cout;
                *reinterpret_cast<__half2*>(C + (size_t)rm * N + cn) = __floats2half2_rn(v0, v1);
                *reinterpret_cast<__half2*>(C + (size_t)(rm + 8) * N + cn) = __floats2half2_rn(v2, v3);
            } else {
                float* C = (float*)Cout;
                float2 o0 = {v0, v1}, o1 = {v2, v3};
                *reinterpret_cast<float2*>(C + (size_t)rm * N + cn) = o0;
                *reinterpret_cast<float2*>(C + (size_t)(rm + 8) * N + cn) = o1;
            }
        }
    }
}

// ====== fused QKV GEMM (NT, fp16 out), 512 threads, warp tile 32x32 ========
__global__ __launch_bounds__(512, 2)
void hgemm_qkv(const __half* __restrict__ h16,
               const __half* __restrict__ kv16,
               const __half* __restrict__ ipw16,
               const float* __restrict__ ipb,
               __half* __restrict__ qo,
               __half* __restrict__ ko,
               __half* __restrict__ vo) {
    __shared__ __half sm[4 * HSTG];
    const uint32_t sm_u32 = (uint32_t)__cvta_generic_to_shared(sm);
    __half* As = sm;
    __half* Bs = sm + 2 * HSTG;

    const int y = blockIdx.y;
    int seg, my;
    if (y < 64)      { seg = 0; my = y; }
    else if (y < 84) { seg = 1; my = y - 64; }
    else             { seg = 2; my = y - 84; }
    const __half* A = (seg == 0) ? h16 : kv16;
    const __half* B = ipw16 + (size_t)seg * DD * DD;
    const float* bias = ipb + seg * DD;
    __half* C = (seg == 0) ? qo : ((seg == 1) ? ko : vo);
    const int K = DD, N = DD;
    const int m0 = my * 128;
    const int n0 = blockIdx.x * 128;

    const int tid  = threadIdx.x;       // 512
    const int lane = tid & 31;
    const int wid  = tid >> 5;
    const int wm = (wid & 3) * 32;
    const int wn = (wid >> 2) * 32;
    const int lm = lane >> 2;
    const int lk = lane & 3;

    float acc[2][4][4];
    #pragma unroll
    for (int i = 0; i < 2; i++)
        #pragma unroll
        for (int j = 0; j < 4; j++)
            #pragma unroll
            for (int f = 0; f < 4; f++) acc[i][j][f] = 0.0f;

    auto issue = [&](int k0, int buf) {
        int r = tid >> 2, c = (tid & 3) * 8;
        cp16(&As[buf * HSTG + r * HA_STRIDE + c],
             A + (size_t)(m0 + r) * K + k0 + c);
        cp16(&Bs[buf * HSTG + r * HA_STRIDE + c],
             B + (size_t)(n0 + r) * K + k0 + c);
    };

    issue(0, 0);
    cp_commit();
    cp_wait0();
    __syncthreads();

    const int a_row  = lane & 15;
    const int a_colh = ((lane >> 4) << 3);

    const int T = K >> 5;
    for (int t = 0; t < T; t++) {
        const int buf = t & 1;
        if (t + 1 < T) { issue((t + 1) << 5, buf ^ 1); cp_commit(); }

        const uint32_t Au = sm_u32 + 2u * (uint32_t)(buf * HSTG);
        const uint32_t Bu = sm_u32 + 2u * (uint32_t)((2 + buf) * HSTG);

        #pragma unroll
        for (int ks = 0; ks < 2; ks++) {
            uint32_t a[2][4];
            #pragma unroll
            for (int mi = 0; mi < 2; mi++) {
                uint32_t addr = Au + 2 * ((wm + mi * 16 + a_row) * HA_STRIDE + ks * 16 + a_colh);
                ldsm4(a[mi][0], a[mi][1], a[mi][2], a[mi][3], addr);
            }
            uint32_t b[4][2];
            #pragma unroll
            for (int p = 0; p < 2; p++) {
                uint32_t r0, r1, r2, r3;
                uint32_t addr = Bu + 2 * ((wn + p * 16 + a_row) * HA_STRIDE + ks * 16 + a_colh);
                ldsm4(r0, r1, r2, r3, addr);
                b[p * 2 + 0][0] = r0; b[p * 2 + 0][1] = r2;
                b[p * 2 + 1][0] = r1; b[p * 2 + 1][1] = r3;
            }
            #pragma unroll
            for (int mi = 0; mi < 2; mi++)
                #pragma unroll
                for (int ni = 0; ni < 4; ni++)
                    mma_f16(acc[mi][ni], a[mi], b[ni]);
        }

        if (t + 1 < T) { cp_wait0(); __syncthreads(); }
    }

    #pragma unroll
    for (int ni = 0; ni < 4; ni++) {
        const int cn = n0 + wn + ni * 8 + lk * 2;
        const float bx = bias[cn], by = bias[cn + 1];
        #pragma unroll
        for (int mi = 0; mi < 2; mi++) {
            const int rm = m0 + wm + mi * 16 + lm;
            *reinterpret_cast<__half2*>(C + (size_t)rm * N + cn) =
                __floats2half2_rn(acc[mi][ni][0] + bx, acc[mi][ni][1] + by);
            *reinterpret_cast<__half2*>(C + (size_t)(rm + 8) * N + cn) =
                __floats2half2_rn(acc[mi][ni][2] + bx, acc[mi][ni][3] + by);
        }
    }
}

// ====== flash attention: fp16 mma, 128 q/block, V via ldsm4t (no vtrans) ====
#define FA_STR 72   // halfs per smem row (64 + 8 pad); row pitch 144B
#define FA_Q_OFF 0
#define FA_K_OFF (128 * FA_STR)
#define FA_V_OFF (192 * FA_STR)
#define FA_P_OFF (256 * FA_STR)
#define FA_SMEM_HALFS (384 * FA_STR)

__global__ __launch_bounds__(256)
void fattn16_kernel(const __half* __restrict__ q,
                    const __half* __restrict__ k,
                    const __half* __restrict__ v,
                    __half* __restrict__ o) {
    extern __shared__ __half fsm[];
    __half* Qh = fsm + FA_Q_OFF;
    __half* Kh = fsm + FA_K_OFF;
    __half* Vh = fsm + FA_V_OFF;   // natural [j][d] layout
    __half* Ph = fsm + FA_P_OFF;
    const uint32_t base_u = (uint32_t)__cvta_generic_to_shared(fsm);
    const uint32_t Qu = base_u + 2 * FA_Q_OFF;
    const uint32_t Ku = base_u + 2 * FA_K_OFF;
    const uint32_t Vu = base_u + 2 * FA_V_OFF;
    const uint32_t Pu = base_u + 2 * FA_P_OFF;

    const int bh = blockIdx.y;
    const int b = bh >> 4, hh = bh & 15;
    const int q0 = blockIdx.x * 128;
    const int tid = threadIdx.x, lane = tid & 31, wid = tid >> 5;
    const int lm = lane >> 2, lk = lane & 3;
    const int wm = wid * 16;   // 8 warps -> 128 query rows

    const int a_row  = lane & 15;
    const int a_colh = ((lane >> 4) << 3);
    const int g  = lane >> 3;
    const int lr = lane & 7;
    const int t_krow = ((g >> 1) << 3) + lr;
    const int t_ncol = (g & 1) << 3;

    // load Q tile: 128 rows (scaled by 1/8, exact in fp16)
    {
        const __half2 sc = __floats2half2_rn(0.125f, 0.125f);
        const __half* qg = q + ((size_t)(b * LL + q0)) * DD + hh * DH;
        #pragma unroll
        for (int it = 0; it < 4; it++) {
            int idx = tid + it * 256;          // 0..1023
            int r = idx >> 3, c = (idx & 7) * 8;
            uint4 raw = *reinterpret_cast<const uint4*>(qg + (size_t)r * DD + c);
            __half2* hp = reinterpret_cast<__half2*>(&raw);
            hp[0] = __hmul2(hp[0], sc); hp[1] = __hmul2(hp[1], sc);
            hp[2] = __hmul2(hp[2], sc); hp[3] = __hmul2(hp[3], sc);
            *reinterpret_cast<uint4*>(&Qh[r * FA_STR + c]) = raw;
        }
    }

    float mrow0 = -1e30f, mrow1 = -1e30f, lrow0 = 0.0f, lrow1 = 0.0f;
    float oacc[8][4];
    #pragma unroll
    for (int ni = 0; ni < 8; ni++)
        #pragma unroll
        for (int f = 0; f < 4; f++) oacc[ni][f] = 0.0f;

    const __half* kg = k + ((size_t)(b * NKEY)) * DD + hh * DH;
    const __half* vg = v + ((size_t)(b * NKEY)) * DD + hh * DH;

    for (int kt = 0; kt < NKEY / 64; kt++) {
        __syncthreads();
        #pragma unroll
        for (int it = 0; it < 2; it++) {
            int idx = tid + it * 256;
            int r = idx >> 3, c = (idx & 7) * 8;
            *reinterpret_cast<uint4*>(&Kh[r * FA_STR + c]) =
                *reinterpret_cast<const uint4*>(kg + (size_t)(kt * 64 + r) * DD + c);
            *reinterpret_cast<uint4*>(&Vh[r * FA_STR + c]) =
                *reinterpret_cast<const uint4*>(vg + (size_t)(kt * 64 + r) * DD + c);
        }
        __syncthreads();

        // S = Q @ K^T (fp16 mma)
        float s[8][4];
        #pragma unroll
        for (int ni = 0; ni < 8; ni++)
            #pragma unroll
            for (int f = 0; f < 4; f++) s[ni][f] = 0.0f;

        #pragma unroll
        for (int kk = 0; kk < 4; kk++) {
            uint32_t a[4];
            ldsm4(a[0], a[1], a[2], a[3],
                  Qu + 2 * ((wm + a_row) * FA_STR + kk * 16 + a_colh));
            #pragma unroll
            for (int p = 0; p < 4; p++) {
                uint32_t r0, r1, r2, r3;
                ldsm4(r0, r1, r2, r3,
                      Ku + 2 * ((p * 16 + a_row) * FA_STR + kk * 16 + a_colh));
                uint32_t b0[2] = {r0, r2}, b1[2] = {r1, r3};
                mma_f16(s[p * 2 + 0], a, b0);
                mma_f16(s[p * 2 + 1], a, b1);
            }
        }

        // online softmax (rows lm, lm+8)
        float rm0 = -1e30f, rm1 = -1e30f;
        #pragma unroll
        for (int ni = 0; ni < 8; ni++) {
            rm0 = fmaxf(rm0, fmaxf(s[ni][0], s[ni][1]));
            rm1 = fmaxf(rm1, fmaxf(s[ni][2], s[ni][3]));
        }
        rm0 = fmaxf(rm0, __shfl_xor_sync(0xffffffffu, rm0, 1));
        rm0 = fmaxf(rm0, __shfl_xor_sync(0xffffffffu, rm0, 2));
        rm1 = fmaxf(rm1, __shfl_xor_sync(0xffffffffu, rm1, 1));
        rm1 = fmaxf(rm1, __shfl_xor_sync(0xffffffffu, rm1, 2));

        float nm0 = fmaxf(mrow0, rm0), nm1 = fmaxf(mrow1, rm1);
        float al0 = __expf(mrow0 - nm0), al1 = __expf(mrow1 - nm1);
        mrow0 = nm0; mrow1 = nm1;

        float rs0 = 0.0f, rs1 = 0.0f;
        #pragma unroll
        for (int ni = 0; ni < 8; ni++) {
            s[ni][0] = __expf(s[ni][0] - nm0);
            s[ni][1] = __expf(s[ni][1] - nm0);
            s[ni][2] = __expf(s[ni][2] - nm1);
            s[ni][3] = __expf(s[ni][3] - nm1);
            rs0 += s[ni][0] + s[ni][1];
            rs1 += s[ni][2] + s[ni][3];
        }
        rs0 += __shfl_xor_sync(0xffffffffu, rs0, 1);
        rs0 += __shfl_xor_sync(0xffffffffu, rs0, 2);
        rs1 += __shfl_xor_sync(0xffffffffu, rs1, 1);
        rs1 += __shfl_xor_sync(0xffffffffu, rs1, 2);

        lrow0 = lrow0 * al0 + rs0;
        lrow1 = lrow1 * al1 + rs1;

        #pragma unroll
        for (int ni = 0; ni < 8; ni++) {
            oacc[ni][0] *= al0; oacc[ni][1] *= al0;
            oacc[ni][2] *= al1; oacc[ni][3] *= al1;
        }

        // P -> smem fp16 (own warp rows only)
        #pragma unroll
        for (int ni = 0; ni < 8; ni++) {
            __half* pp = &Ph[(wm + lm) * FA_STR + ni * 8 + 2 * lk];
            *reinterpret_cast<__half2*>(pp) = __floats2half2_rn(s[ni][0], s[ni][1]);
            *reinterpret_cast<__half2*>(pp + 8 * FA_STR) = __floats2half2_rn(s[ni][2], s[ni][3]);
        }
        __syncwarp();

        // O += P @ V : Vh is [j][d] = [K][N] row-major -> ldsm4t (hgemm NN idiom)
        #pragma unroll
        for (int kk = 0; kk < 4; kk++) {
            uint32_t a[4];
            ldsm4(a[0], a[1], a[2], a[3],
                  Pu + 2 * ((wm + a_row) * FA_STR + kk * 16 + a_colh));
            #pragma unroll
            for (int p = 0; p < 4; p++) {
                uint32_t r0, r1, r2, r3;
                ldsm4t(r0, r1, r2, r3,
                       Vu + 2 * ((kk * 16 + t_krow) * FA_STR + p * 16 + t_ncol));
                uint32_t b0[2] = {r0, r2}, b1[2] = {r1, r3};
                mma_f16(oacc[p * 2 + 0], a, b0);
                mma_f16(oacc[p * 2 + 1], a, b1);
            }
        }
    }

    const float inv0 = 1.0f / lrow0, inv1 = 1.0f / lrow1;
    __half* og = o + ((size_t)(b * LL + q0 + wm + lm)) * DD + hh * DH;
    #pragma unroll
    for (int ni = 0; ni < 8; ni++) {
        const int cc = ni * 8 + 2 * lk;
        *reinterpret_cast<__half2*>(og + cc) =
            __floats2half2_rn(oacc[ni][0] * inv0, oacc[ni][1] * inv0);
        *reinterpret_cast<__half2*>(og + (size_t)8 * DD + cc) =
            __floats2half2_rn(oacc[ni][2] * inv1, oacc[ni][3] * inv1);
    }
}

// ---------------- driver ----------------
extern "C" void kernel_launch(void* const* d_in, const int* in_sizes, int n_in,
                              void* d_out, int out_size) {
    const float* x        = (const float*)d_in[0];
    const float* gumbel_u = (const float*)d_in[1];
    const float* ln1_g    = (const float*)d_in[2];
    const float* ln1_b    = (const float*)d_in[3];
    const float* ln2_g    = (const float*)d_in[4];
    const float* ln2_b    = (const float*)d_in[5];
    const float* w_sal    = (const float*)d_in[6];
    const float* b_sal    = (const float*)d_in[7];   // constant shift: cancels, unused
    const float* ipw      = (const float*)d_in[8];
    const float* ipb      = (const float*)d_in[9];
    const float* opw      = (const float*)d_in[10];
    const float* opb      = (const float*)d_in[11];
    const float* w_fc     = (const float*)d_in[12];
    const float* b_fc     = (const float*)d_in[13];
    const float* w_proj   = (const float*)d_in[14];
    const float* b_proj   = (const float*)d_in[15];
    float* out = (float*)d_out;
    (void)b_sal;

    void* p;
    cudaGetSymbolAddress(&p, g_h16);    __half* h16   = (__half*)p;
    cudaGetSymbolAddress(&p, g_kv16);   __half* kv16  = (__half*)p;
    cudaGetSymbolAddress(&p, g_q16);    __half* q16   = (__half*)p;
    cudaGetSymbolAddress(&p, g_k16);    __half* k16   = (__half*)p;
    cudaGetSymbolAddress(&p, g_v16);    __half* v16   = (__half*)p;
    cudaGetSymbolAddress(&p, g_att16);  __half* att16 = (__half*)p;
    cudaGetSymbolAddress(&p, g_x2);     float*  x2    = (float*)p;
    cudaGetSymbolAddress(&p, g_h2_16);  __half* h2_16 = (__half*)p;
    cudaGetSymbolAddress(&p, g_ff16);   __half* ff16  = (__half*)p;
    cudaGetSymbolAddress(&p, g_w16);    __half* w16   = (__half*)p;
    cudaGetSymbolAddress(&p, g_logits); float*  logi  = (float*)p;

    const int FA_SMEM = FA_SMEM_HALFS * 2;   // 55296 bytes
    cudaFuncSetAttribute(fattn16_kernel, cudaFuncAttributeMaxDynamicSharedMemorySize, FA_SMEM);

    // 0. weight prep + logits zeroing
    f2h_all_kernel<<<(W16_TOTAL / 4 + 255) / 256, 256>>>(ipw, opw, w_fc, w_proj, w16);
    cudaMemsetAsync(logi, 0, BB * NB * sizeof(float));
    // 1. LN1 + fused saliency logits (fp16 h out, atomic logits)
    ln1_sal_kernel<<<NTOK, 256>>>(x, ln1_g, ln1_b, w_sal, h16, logi);
    // 2+3. fused selection + gather -> kv16 (reads fp16 h)
    gather_kernel<<<MKV, 256>>>(h16, logi, gumbel_u, kv16);
    // 4. fused QKV projection (fp16 out, 512 threads)
    hgemm_qkv<<<dim3(DD / 128, 64 + 20 + 20), 512>>>(
        h16, kv16, w16 + W16_IPW, ipb, q16, k16, v16);
    // 5. attention (fp16 mma flash, V transposed in-kernel via ldsm4t)
    fattn16_kernel<<<dim3(LL / 128, BB * NH), 256, FA_SMEM>>>(q16, k16, v16, att16);
    // 6. out proj + residual (fp32 out)
    hgemm<true, false, true, false><<<dim3(DD / 128, NTOK / 128), 512>>>(
        att16, w16 + W16_OPW, opb, x, x2, NTOK, DD, DD);
    // 7. LN2 (fp16 out)
    ln2_kernel<<<NTOK, 256>>>(x2, ln2_g, ln2_b, h2_16);
    // 8. FFN up + gelu (NN, fp16 out)
    hgemm<false, true, false, true><<<dim3(DFFN / 128, NTOK / 128), 512>>>(
        h2_16, w16 + W16_WFC, b_fc, nullptr, ff16, NTOK, DFFN, DD);
    // 9. FFN down + residual (NN, fp32 out) -> out
    hgemm<false, false, true, false><<<dim3(DD / 128, NTOK / 128), 512>>>(
        ff16, w16 + W16_WPROJ, b_proj, x2, out, NTOK, DD, DFFN);
}

// round 16
// speedup vs baseline: 1.0366x; 1.0046x over previous
#include <cuda_runtime.h>
#include <cuda_fp16.h>
#include <math.h>
#include <stdint.h>

// ---------------- problem constants ----------------
#define DD     1024
#define LL     2048
#define BB     4
#define NH     16
#define DH     64
#define SSEL   5
#define WWIN   128
#define BKBLK  32
#define NB     64          // L / BK
#define NTOK   8192        // B*L
#define MKV    2560        // B*S*W
#define NKEY   640         // S*W keys per batch
#define DFFN   4096

// ---------------- scratch (device globals; no allocations allowed) --------
__device__ __half g_h16 [NTOK * DD];
__device__ __half g_kv16[MKV  * DD];
__device__ __half g_q16 [NTOK * DD];
__device__ __half g_k16 [MKV  * DD];
__device__ __half g_v16 [MKV  * DD];
__device__ __half g_att16[NTOK * DD];
__device__ float  g_x2  [NTOK * DD];
__device__ __half g_h2_16[NTOK * DD];
__device__ __half g_ff16 [NTOK * DFFN];
__device__ __half g_w16  [12582912];     // fp16 weights: ipw | opw | w_fc | w_proj
__device__ float  g_logits[BB * NB];

#define W16_IPW   0
#define W16_OPW   3145728
#define W16_WFC   4194304
#define W16_WPROJ 8388608
#define W16_TOTAL 12582912

// ---------------- helpers ----------------
__device__ __forceinline__ void mma_f16(float* d, const uint32_t* a, const uint32_t* b) {
    asm volatile(
        "mma.sync.aligned.m16n8k16.row.col.f32.f16.f16.f32 "
        "{%0,%1,%2,%3}, {%4,%5,%6,%7}, {%8,%9}, {%0,%1,%2,%3};\n"
        : "+f"(d[0]), "+f"(d[1]), "+f"(d[2]), "+f"(d[3])
        : "r"(a[0]), "r"(a[1]), "r"(a[2]), "r"(a[3]), "r"(b[0]), "r"(b[1]));
}

__device__ __forceinline__ void ldsm4(uint32_t& r0, uint32_t& r1, uint32_t& r2, uint32_t& r3,
                                      uint32_t addr) {
    asm volatile("ldmatrix.sync.aligned.m8n8.x4.shared.b16 {%0,%1,%2,%3}, [%4];"
                 : "=r"(r0), "=r"(r1), "=r"(r2), "=r"(r3) : "r"(addr));
}
__device__ __forceinline__ void ldsm4t(uint32_t& r0, uint32_t& r1, uint32_t& r2, uint32_t& r3,
                                       uint32_t addr) {
    asm volatile("ldmatrix.sync.aligned.m8n8.x4.trans.shared.b16 {%0,%1,%2,%3}, [%4];"
                 : "=r"(r0), "=r"(r1), "=r"(r2), "=r"(r3) : "r"(addr));
}

__device__ __forceinline__ void cp16(void* s, const void* g) {
    unsigned sa = (unsigned)__cvta_generic_to_shared(s);
    asm volatile("cp.async.cg.shared.global [%0], [%1], 16;\n" :: "r"(sa), "l"(g));
}
__device__ __forceinline__ void cp_commit() { asm volatile("cp.async.commit_group;\n"); }
__device__ __forceinline__ void cp_wait0()  { asm volatile("cp.async.wait_group 0;\n"); }

// fast gelu (tanh-approx form, computed via sigmoid identity):
// 0.5*v*(1+tanh(u)) == v * sigmoid(2u) == v / (1 + exp(-2u))
__device__ __forceinline__ float gelu_fast(float v) {
    float u = 0.7978845608028654f * (v + 0.044715f * v * v * v);
    return v / (1.0f + __expf(-2.0f * u));
}

// ---------------- fused fp32 -> fp16 weight conversion ----------------
__global__ void f2h_all_kernel(const float* __restrict__ ipw,
                               const float* __restrict__ opw,
                               const float* __restrict__ wfc,
                               const float* __restrict__ wproj,
                               __half* __restrict__ w16) {
    int i = (blockIdx.x * blockDim.x + threadIdx.x) * 4;
    if (i >= W16_TOTAL) return;
    const float* src;
    if (i < W16_OPW)        src = ipw + i;
    else if (i < W16_WFC)   src = opw + (i - W16_OPW);
    else if (i < W16_WPROJ) src = wfc + (i - W16_WFC);
    else                    src = wproj + (i - W16_WPROJ);
    float4 v = *reinterpret_cast<const float4*>(src);
    __half2* d = reinterpret_cast<__half2*>(w16 + i);
    d[0] = __floats2half2_rn(v.x, v.y);
    d[1] = __floats2half2_rn(v.z, v.w);
}

// ---------- LN1 + fused saliency: one block per token ----------
__global__ void ln1_sal_kernel(const float* __restrict__ x,
                               const float* __restrict__ gam,
                               const float* __restrict__ bet,
                               const float* __restrict__ w_sal,
                               __half* __restrict__ out16,
                               float* __restrict__ logits) {
    __shared__ float red[8];
    const int row = blockIdx.x;
    const int t = threadIdx.x;  // 256
    const float4* xr = reinterpret_cast<const float4*>(x) + (size_t)row * (DD / 4);
    float4 v = xr[t];

    float s = v.x + v.y + v.z + v.w;
    #pragma unroll
    for (int o = 16; o; o >>= 1) s += __shfl_down_sync(0xffffffffu, s, o);
    if ((t & 31) == 0) red[t >> 5] = s;
    __syncthreads();
    float tot = red[0] + red[1] + red[2] + red[3] + red[4] + red[5] + red[6] + red[7];
    const float mean = tot * (1.0f / DD);
    __syncthreads();

    float dx = v.x - mean, dy = v.y - mean, dz = v.z - mean, dw = v.w - mean;
    float sq = dx * dx + dy * dy + dz * dz + dw * dw;
    #pragma unroll
    for (int o = 16; o; o >>= 1) sq += __shfl_down_sync(0xffffffffu, sq, o);
    if ((t & 31) == 0) red[t >> 5] = sq;
    __syncthreads();
    float var = (red[0] + red[1] + red[2] + red[3] + red[4] + red[5] + red[6] + red[7]) * (1.0f / DD);
    const float r = rsqrtf(var + 1e-5f);

    const float4 gg = reinterpret_cast<const float4*>(gam)[t];
    const float4 bb = reinterpret_cast<const float4*>(bet)[t];
    float4 o4;
    o4.x = dx * r * gg.x + bb.x;
    o4.y = dy * r * gg.y + bb.y;
    o4.z = dz * r * gg.z + bb.z;
    o4.w = dw * r * gg.w + bb.w;
    __half2* d = reinterpret_cast<__half2*>(out16 + (size_t)row * DD + t * 4);
    d[0] = __floats2half2_rn(o4.x, o4.y);
    d[1] = __floats2half2_rn(o4.z, o4.w);

    const float4 ws = reinterpret_cast<const float4*>(w_sal)[t];
    float dsal = o4.x * ws.x + o4.y * ws.y + o4.z * ws.z + o4.w * ws.w;
    __syncthreads();
    #pragma unroll
    for (int o = 16; o; o >>= 1) dsal += __shfl_down_sync(0xffffffffu, dsal, o);
    if ((t & 31) == 0) red[t >> 5] = dsal;
    __syncthreads();
    if (t == 0) {
        float dtot = red[0] + red[1] + red[2] + red[3] + red[4] + red[5] + red[6] + red[7];
        atomicAdd(&logits[row >> 5], dtot * (1.0f / BKBLK));
    }
}

// ---------------- LayerNorm (LN2): one block per token, fp16 out ----------
__global__ void ln2_kernel(const float* __restrict__ x,
                           const float* __restrict__ gam,
                           const float* __restrict__ bet,
                           __half* __restrict__ out16) {
    __shared__ float red[8];
    const int row = blockIdx.x;
    const int t = threadIdx.x;  // 256
    const float4* xr = reinterpret_cast<const float4*>(x) + (size_t)row * (DD / 4);
    float4 v = xr[t];

    float s = v.x + v.y + v.z + v.w;
    #pragma unroll
    for (int o = 16; o; o >>= 1) s += __shfl_down_sync(0xffffffffu, s, o);
    if ((t & 31) == 0) red[t >> 5] = s;
    __syncthreads();
    float tot = red[0] + red[1] + red[2] + red[3] + red[4] + red[5] + red[6] + red[7];
    const float mean = tot * (1.0f / DD);
    __syncthreads();

    float dx = v.x - mean, dy = v.y - mean, dz = v.z - mean, dw = v.w - mean;
    float sq = dx * dx + dy * dy + dz * dz + dw * dw;
    #pragma unroll
    for (int o = 16; o; o >>= 1) sq += __shfl_down_sync(0xffffffffu, sq, o);
    if ((t & 31) == 0) red[t >> 5] = sq;
    __syncthreads();
    float var = (red[0] + red[1] + red[2] + red[3] + red[4] + red[5] + red[6] + red[7]) * (1.0f / DD);
    const float r = rsqrtf(var + 1e-5f);

    const float4 gg = reinterpret_cast<const float4*>(gam)[t];
    const float4 bb = reinterpret_cast<const float4*>(bet)[t];
    __half2* d = reinterpret_cast<__half2*>(out16 + (size_t)row * DD + t * 4);
    d[0] = __floats2half2_rn(dx * r * gg.x + bb.x, dy * r * gg.y + bb.y);
    d[1] = __floats2half2_rn(dz * r * gg.z + bb.z, dw * r * gg.w + bb.w);
}

// -------- fused selection + window gather (fp16 in/out) --------
__global__ void gather_kernel(const __half* __restrict__ h16,
                              const float* __restrict__ logits,
                              const float* __restrict__ gu,
                              __half* __restrict__ kv) {
    __shared__ int   s_start;
    __shared__ float s_scale;

    const int row = blockIdx.x;          // b*640 + s*128 + w
    const int b = row / (SSEL * WWIN);
    const int r = row % (SSEL * WWIN);
    const int s = r / WWIN;
    const int w = r % WWIN;
    const int sb = s * BB + b;
    const int t = threadIdx.x;           // 256

    if (t < 32) {
        const int lane = t;
        float u0 = gu[sb * NB + lane];
        float u1 = gu[sb * NB + 32 + lane];
        float g0 = -logf(-logf(u0 + 1e-9f) + 1e-9f);
        float g1 = -logf(-logf(u1 + 1e-9f) + 1e-9f);
        float p0 = logits[b * NB + lane] + g0;       // TAU = 1, b_sal shift dropped
        float p1 = logits[b * NB + 32 + lane] + g1;

        float m = p0; int idx = lane;
        if (p1 > m) { m = p1; idx = lane + 32; }
        #pragma unroll
        for (int o = 16; o; o >>= 1) {
            float om = __shfl_down_sync(0xffffffffu, m, o);
            int   oi = __shfl_down_sync(0xffffffffu, idx, o);
            if (om > m || (om == m && oi < idx)) { m = om; idx = oi; }
        }
        m   = __shfl_sync(0xffffffffu, m, 0);
        idx = __shfl_sync(0xffffffffu, idx, 0);

        float se = expf(p0 - m) + expf(p1 - m);
        #pragma unroll
        for (int o = 16; o; o >>= 1) se += __shfl_down_sync(0xffffffffu, se, o);
        if (lane == 0) {
            float ww = 1.0f / se;
            float scale = (1.0f + ww) - ww;
            int start = idx * BKBLK + BKBLK / 2 - WWIN / 2;
            if (start < 0) start = 0;
            if (start > LL - WWIN) start = LL - WWIN;
            s_start = start;
            s_scale = scale;
        }
    }
    __syncthreads();

    const int src = b * LL + s_start + w;
    const __half2 sc2 = __float2half2_rn(s_scale);
    uint2 raw = *reinterpret_cast<const uint2*>(h16 + (size_t)src * DD + t * 4);
    __half2* hp = reinterpret_cast<__half2*>(&raw);
    hp[0] = __hmul2(hp[0], sc2);
    hp[1] = __hmul2(hp[1], sc2);
    *reinterpret_cast<uint2*>(kv + (size_t)row * DD + t * 4) = raw;
}

// ===== FP16 tensor-core GEMM: 512 threads, warp tile 32x32, 2-stage ========
#define HA_STRIDE 40     // halfs
#define HB_NN_STRIDE 136 // halfs
#define HSTG 5120        // halfs per tile stage

template<bool BT, bool GELU, bool RES, bool OUTH>
__global__ __launch_bounds__(512, 2)
void hgemm(const __half* __restrict__ A,
           const __half* __restrict__ B,
           const float* __restrict__ bias,
           const float* __restrict__ res,
           void* __restrict__ Cout,
           int M, int N, int K) {
    __shared__ __half sm[4 * HSTG];
    const uint32_t sm_u32 = (uint32_t)__cvta_generic_to_shared(sm);
    __half* As = sm;
    __half* Bs = sm + 2 * HSTG;

    const int tid  = threadIdx.x;       // 512
    const int lane = tid & 31;
    const int wid  = tid >> 5;          // 0..15
    const int wm = (wid & 3) * 32;      // 4 warps along M
    const int wn = (wid >> 2) * 32;     // 4 warps along N
    const int lm = lane >> 2;
    const int lk = lane & 3;
    const int m0 = blockIdx.y * 128;
    const int n0 = blockIdx.x * 128;

    float acc[2][4][4];
    #pragma unroll
    for (int i = 0; i < 2; i++)
        #pragma unroll
        for (int j = 0; j < 4; j++)
            #pragma unroll
            for (int f = 0; f < 4; f++) acc[i][j][f] = 0.0f;

    auto issue = [&](int k0, int buf) {
        {
            int r = tid >> 2, c = (tid & 3) * 8;      // 512 granules exactly
            cp16(&As[buf * HSTG + r * HA_STRIDE + c],
                 A + (size_t)(m0 + r) * K + k0 + c);
        }
        if (BT) {
            int r = tid >> 2, c = (tid & 3) * 8;
            cp16(&Bs[buf * HSTG + r * HA_STRIDE + c],
                 B + (size_t)(n0 + r) * K + k0 + c);
        } else {
            int r = tid >> 4, c = (tid & 15) * 8;
            cp16(&Bs[buf * HSTG + r * HB_NN_STRIDE + c],
                 B + (size_t)(k0 + r) * N + n0 + c);
        }
    };

    issue(0, 0);
    cp_commit();
    cp_wait0();
    __syncthreads();

    const int a_row  = lane & 15;
    const int a_colh = ((lane >> 4) << 3);
    const int g  = lane >> 3;
    const int lr = lane & 7;
    const int t_krow = ((g >> 1) << 3) + lr;
    const int t_ncol = (g & 1) << 3;

    const int T = K >> 5;
    for (int t = 0; t < T; t++) {
        const int buf = t & 1;
        if (t + 1 < T) { issue((t + 1) << 5, buf ^ 1); cp_commit(); }

        const uint32_t Au = sm_u32 + 2u * (uint32_t)(buf * HSTG);
        const uint32_t Bu = sm_u32 + 2u * (uint32_t)((2 + buf) * HSTG);

        #pragma unroll
        for (int ks = 0; ks < 2; ks++) {
            uint32_t a[2][4];
            #pragma unroll
            for (int mi = 0; mi < 2; mi++) {
                uint32_t addr = Au + 2 * ((wm + mi * 16 + a_row) * HA_STRIDE + ks * 16 + a_colh);
                ldsm4(a[mi][0], a[mi][1], a[mi][2], a[mi][3], addr);
            }
            uint32_t b[4][2];
            #pragma unroll
            for (int p = 0; p < 2; p++) {
                uint32_t r0, r1, r2, r3;
                if (BT) {
                    uint32_t addr = Bu + 2 * ((wn + p * 16 + a_row) * HA_STRIDE + ks * 16 + a_colh);
                    ldsm4(r0, r1, r2, r3, addr);
                } else {
                    uint32_t addr = Bu + 2 * ((ks * 16 + t_krow) * HB_NN_STRIDE + wn + p * 16 + t_ncol);
                    ldsm4t(r0, r1, r2, r3, addr);
                }
                b[p * 2 + 0][0] = r0; b[p * 2 + 0][1] = r2;
                b[p * 2 + 1][0] = r1; b[p * 2 + 1][1] = r3;
            }
            #pragma unroll
            for (int mi = 0; mi < 2; mi++)
                #pragma unroll
                for (int ni = 0; ni < 4; ni++)
                    mma_f16(acc[mi][ni], a[mi], b[ni]);
        }

        if (t + 1 < T) { cp_wait0(); __syncthreads(); }
    }

    #pragma unroll
    for (int ni = 0; ni < 4; ni++) {
        const int cn = n0 + wn + ni * 8 + lk * 2;
        const float bx = bias[cn], by = bias[cn + 1];
        #pragma unroll
        for (int mi = 0; mi < 2; mi++) {
            const int rm = m0 + wm + mi * 16 + lm;
            float v0 = acc[mi][ni][0] + bx;
            float v1 = acc[mi][ni][1] + by;
            float v2 = acc[mi][ni][2] + bx;
            float v3 = acc[mi][ni][3] + by;
            if (GELU) {
                v0 = gelu_fast(v0); v1 = gelu_fast(v1);
                v2 = gelu_fast(v2); v3 = gelu_fast(v3);
            }
            if (RES) {
                const float* rf = (const float*)res;
                float2 r0 = *reinterpret_cast<const float2*>(rf + (size_t)rm * N + cn);
                float2 r1 = *reinterpret_cast<const float2*>(rf + (size_t)(rm + 8) * N + cn);
                v0 += r0.x; v1 += r0.y; v2 += r1.x; v3 += r1.y;
            }
            if (OUTH) {
                __half* C = (__half*)Cout;
                *reinterpret_cast<__half2*>(C + (size_t)rm * N + cn) = __floats2half2_rn(v0, v1);
                *reinterpret_cast<__half2*>(C + (size_t)(rm + 8) * N + cn) = __floats2half2_rn(v2, v3);
            } else {
                float* C = (float*)Cout;
                float2 o0 = {v0, v1}, o1 = {v2, v3};
                *reinterpret_cast<float2*>(C + (size_t)rm * N + cn) = o0;
                *reinterpret_cast<float2*>(C + (size_t)(rm + 8) * N + cn) = o1;
            }
        }
    }
}

// ====== fused QKV GEMM (NT, fp16 out), 512 threads, warp tile 32x32 ========
__global__ __launch_bounds__(512, 2)
void hgemm_qkv(const __half* __restrict__ h16,
               const __half* __restrict__ kv16,
               const __half* __restrict__ ipw16,
               const float* __restrict__ ipb,
               __half* __restrict__ qo,
               __half* __restrict__ ko,
               __half* __restrict__ vo) {
    __shared__ __half sm[4 * HSTG];
    const uint32_t sm_u32 = (uint32_t)__cvta_generic_to_shared(sm);
    __half* As = sm;
    __half* Bs = sm + 2 * HSTG;

    const int y = blockIdx.y;
    int seg, my;
    if (y < 64)      { seg = 0; my = y; }
    else if (y < 84) { seg = 1; my = y - 64; }
    else             { seg = 2; my = y - 84; }
    const __half* A = (seg == 0) ? h16 : kv16;
    const __half* B = ipw16 + (size_t)seg * DD * DD;
    const float* bias = ipb + seg * DD;
    __half* C = (seg == 0) ? qo : ((seg == 1) ? ko : vo);
    const int K = DD, N = DD;
    const int m0 = my * 128;
    const int n0 = blockIdx.x * 128;

    const int tid  = threadIdx.x;       // 512
    const int lane = tid & 31;
    const int wid  = tid >> 5;
    const int wm = (wid & 3) * 32;
    const int wn = (wid >> 2) * 32;
    const int lm = lane >> 2;
    const int lk = lane & 3;

    float acc[2][4][4];
    #pragma unroll
    for (int i = 0; i < 2; i++)
        #pragma unroll
        for (int j = 0; j < 4; j++)
            #pragma unroll
            for (int f = 0; f < 4; f++) acc[i][j][f] = 0.0f;

    auto issue = [&](int k0, int buf) {
        int r = tid >> 2, c = (tid & 3) * 8;
        cp16(&As[buf * HSTG + r * HA_STRIDE + c],
             A + (size_t)(m0 + r) * K + k0 + c);
        cp16(&Bs[buf * HSTG + r * HA_STRIDE + c],
             B + (size_t)(n0 + r) * K + k0 + c);
    };

    issue(0, 0);
    cp_commit();
    cp_wait0();
    __syncthreads();

    const int a_row  = lane & 15;
    const int a_colh = ((lane >> 4) << 3);

    const int T = K >> 5;
    for (int t = 0; t < T; t++) {
        const int buf = t & 1;
        if (t + 1 < T) { issue((t + 1) << 5, buf ^ 1); cp_commit(); }

        const uint32_t Au = sm_u32 + 2u * (uint32_t)(buf * HSTG);
        const uint32_t Bu = sm_u32 + 2u * (uint32_t)((2 + buf) * HSTG);

        #pragma unroll
        for (int ks = 0; ks < 2; ks++) {
            uint32_t a[2][4];
            #pragma unroll
            for (int mi = 0; mi < 2; mi++) {
                uint32_t addr = Au + 2 * ((wm + mi * 16 + a_row) * HA_STRIDE + ks * 16 + a_colh);
                ldsm4(a[mi][0], a[mi][1], a[mi][2], a[mi][3], addr);
            }
            uint32_t b[4][2];
            #pragma unroll
            for (int p = 0; p < 2; p++) {
                uint32_t r0, r1, r2, r3;
                uint32_t addr = Bu + 2 * ((wn + p * 16 + a_row) * HA_STRIDE + ks * 16 + a_colh);
                ldsm4(r0, r1, r2, r3, addr);
                b[p * 2 + 0][0] = r0; b[p * 2 + 0][1] = r2;
                b[p * 2 + 1][0] = r1; b[p * 2 + 1][1] = r3;
            }
            #pragma unroll
            for (int mi = 0; mi < 2; mi++)
                #pragma unroll
                for (int ni = 0; ni < 4; ni++)
                    mma_f16(acc[mi][ni], a[mi], b[ni]);
        }

        if (t + 1 < T) { cp_wait0(); __syncthreads(); }
    }

    #pragma unroll
    for (int ni = 0; ni < 4; ni++) {
        const int cn = n0 + wn + ni * 8 + lk * 2;
        const float bx = bias[cn], by = bias[cn + 1];
        #pragma unroll
        for (int mi = 0; mi < 2; mi++) {
            const int rm = m0 + wm + mi * 16 + lm;
            *reinterpret_cast<__half2*>(C + (size_t)rm * N + cn) =
                __floats2half2_rn(acc[mi][ni][0] + bx, acc[mi][ni][1] + by);
            *reinterpret_cast<__half2*>(C + (size_t)(rm + 8) * N + cn) =
                __floats2half2_rn(acc[mi][ni][2] + bx, acc[mi][ni][3] + by);
        }
    }
}

// ====== flash attention: fp16 mma, 128 q/block, V via ldsm4t (no vtrans) ====
#define FA_STR 72   // halfs per smem row (64 + 8 pad); row pitch 144B
#define FA_Q_OFF 0
#define FA_K_OFF (128 * FA_STR)
#define FA_V_OFF (192 * FA_STR)
#define FA_P_OFF (256 * FA_STR)
#define FA_SMEM_HALFS (384 * FA_STR)

__global__ __launch_bounds__(256)
void fattn16_kernel(const __half* __restrict__ q,
                    const __half* __restrict__ k,
                    const __half* __restrict__ v,
                    __half* __restrict__ o) {
    extern __shared__ __half fsm[];
    __half* Qh = fsm + FA_Q_OFF;
    __half* Kh = fsm + FA_K_OFF;
    __half* Vh = fsm + FA_V_OFF;   // natural [j][d] layout
    __half* Ph = fsm + FA_P_OFF;
    const uint32_t base_u = (uint32_t)__cvta_generic_to_shared(fsm);
    const uint32_t Qu = base_u + 2 * FA_Q_OFF;
    const uint32_t Ku = base_u + 2 * FA_K_OFF;
    const uint32_t Vu = base_u + 2 * FA_V_OFF;
    const uint32_t Pu = base_u + 2 * FA_P_OFF;

    const int bh = blockIdx.y;
    const int b = bh >> 4, hh = bh & 15;
    const int q0 = blockIdx.x * 128;
    const int tid = threadIdx.x, lane = tid & 31, wid = tid >> 5;
    const int lm = lane >> 2, lk = lane & 3;
    const int wm = wid * 16;   // 8 warps -> 128 query rows

    const int a_row  = lane & 15;
    const int a_colh = ((lane >> 4) << 3);
    const int g  = lane >> 3;
    const int lr = lane & 7;
    const int t_krow = ((g >> 1) << 3) + lr;
    const int t_ncol = (g & 1) << 3;

    // load Q tile: 128 rows (scaled by 1/8, exact in fp16)
    {
        const __half2 sc = __floats2half2_rn(0.125f, 0.125f);
        const __half* qg = q + ((size_t)(b * LL + q0)) * DD + hh * DH;
        #pragma unroll
        for (int it = 0; it < 4; it++) {
            int idx = tid + it * 256;          // 0..1023
            int r = idx >> 3, c = (idx & 7) * 8;
            uint4 raw = *reinterpret_cast<const uint4*>(qg + (size_t)r * DD + c);
            __half2* hp = reinterpret_cast<__half2*>(&raw);
            hp[0] = __hmul2(hp[0], sc); hp[1] = __hmul2(hp[1], sc);
            hp[2] = __hmul2(hp[2], sc); hp[3] = __hmul2(hp[3], sc);
            *reinterpret_cast<uint4*>(&Qh[r * FA_STR + c]) = raw;
        }
    }

    float mrow0 = -1e30f, mrow1 = -1e30f, lrow0 = 0.0f, lrow1 = 0.0f;
    float oacc[8][4];
    #pragma unroll
    for (int ni = 0; ni < 8; ni++)
        #pragma unroll
        for (int f = 0; f < 4; f++) oacc[ni][f] = 0.0f;

    const __half* kg = k + ((size_t)(b * NKEY)) * DD + hh * DH;
    const __half* vg = v + ((size_t)(b * NKEY)) * DD + hh * DH;

    for (int kt = 0; kt < NKEY / 64; kt++) {
        __syncthreads();
        #pragma unroll
        for (int it = 0; it < 2; it++) {
            int idx = tid + it * 256;
            int r = idx >> 3, c = (idx & 7) * 8;
            *reinterpret_cast<uint4*>(&Kh[r * FA_STR + c]) =
                *reinterpret_cast<const uint4*>(kg + (size_t)(kt * 64 + r) * DD + c);
            *reinterpret_cast<uint4*>(&Vh[r * FA_STR + c]) =
                *reinterpret_cast<const uint4*>(vg + (size_t)(kt * 64 + r) * DD + c);
        }
        __syncthreads();

        // S = Q @ K^T (fp16 mma)
        float s[8][4];
        #pragma unroll
        for (int ni = 0; ni < 8; ni++)
            #pragma unroll
            for (int f = 0; f < 4; f++) s[ni][f] = 0.0f;

        #pragma unroll
        for (int kk = 0; kk < 4; kk++) {
            uint32_t a[4];
            ldsm4(a[0], a[1], a[2], a[3],
                  Qu + 2 * ((wm + a_row) * FA_STR + kk * 16 + a_colh));
            #pragma unroll
            for (int p = 0; p < 4; p++) {
                uint32_t r0, r1, r2, r3;
                ldsm4(r0, r1, r2, r3,
                      Ku + 2 * ((p * 16 + a_row) * FA_STR + kk * 16 + a_colh));
                uint32_t b0[2] = {r0, r2}, b1[2] = {r1, r3};
                mma_f16(s[p * 2 + 0], a, b0);
                mma_f16(s[p * 2 + 1], a, b1);
            }
        }

        // online softmax (rows lm, lm+8)
        float rm0 = -1e30f, rm1 = -1e30f;
        #pragma unroll
        for (int ni = 0; ni < 8; ni++) {
            rm0 = fmaxf(rm0, fmaxf(s[ni][0], s[ni][1]));
            rm1 = fmaxf(rm1, fmaxf(s[ni][2], s[ni][3]));
        }
        rm0 = fmaxf(rm0, __shfl_xor_sync(0xffffffffu, rm0, 1));
        rm0 = fmaxf(rm0, __shfl_xor_sync(0xffffffffu, rm0, 2));
        rm1 = fmaxf(rm1, __shfl_xor_sync(0xffffffffu, rm1, 1));
        rm1 = fmaxf(rm1, __shfl_xor_sync(0xffffffffu, rm1, 2));

        float nm0 = fmaxf(mrow0, rm0), nm1 = fmaxf(mrow1, rm1);
        float al0 = __expf(mrow0 - nm0), al1 = __expf(mrow1 - nm1);
        mrow0 = nm0; mrow1 = nm1;

        float rs0 = 0.0f, rs1 = 0.0f;
        #pragma unroll
        for (int ni = 0; ni < 8; ni++) {
            s[ni][0] = __expf(s[ni][0] - nm0);
            s[ni][1] = __expf(s[ni][1] - nm0);
            s[ni][2] = __expf(s[ni][2] - nm1);
            s[ni][3] = __expf(s[ni][3] - nm1);
            rs0 += s[ni][0] + s[ni][1];
            rs1 += s[ni][2] + s[ni][3];
        }
        rs0 += __shfl_xor_sync(0xffffffffu, rs0, 1);
        rs0 += __shfl_xor_sync(0xffffffffu, rs0, 2);
        rs1 += __shfl_xor_sync(0xffffffffu, rs1, 1);
        rs1 += __shfl_xor_sync(0xffffffffu, rs1, 2);

        lrow0 = lrow0 * al0 + rs0;
        lrow1 = lrow1 * al1 + rs1;

        #pragma unroll
        for (int ni = 0; ni < 8; ni++) {
            oacc[ni][0] *= al0; oacc[ni][1] *= al0;
            oacc[ni][2] *= al1; oacc[ni][3] *= al1;
        }

        // P -> smem fp16 (own warp rows only)
        #pragma unroll
        for (int ni = 0; ni < 8; ni++) {
            __half* pp = &Ph[(wm + lm) * FA_STR + ni * 8 + 2 * lk];
            *reinterpret_cast<__half2*>(pp) = __floats2half2_rn(s[ni][0], s[ni][1]);
            *reinterpret_cast<__half2*>(pp + 8 * FA_STR) = __floats2half2_rn(s[ni][2], s[ni][3]);
        }
        __syncwarp();

        // O += P @ V : Vh is [j][d] = [K][N] row-major -> ldsm4t (hgemm NN idiom)
        #pragma unroll
        for (int kk = 0; kk < 4; kk++) {
            uint32_t a[4];
            ldsm4(a[0], a[1], a[2], a[3],
                  Pu + 2 * ((wm + a_row) * FA_STR + kk * 16 + a_colh));
            #pragma unroll
            for (int p = 0; p < 4; p++) {
                uint32_t r0, r1, r2, r3;
                ldsm4t(r0, r1, r2, r3,
                       Vu + 2 * ((kk * 16 + t_krow) * FA_STR + p * 16 + t_ncol));
                uint32_t b0[2] = {r0, r2}, b1[2] = {r1, r3};
                mma_f16(oacc[p * 2 + 0], a, b0);
                mma_f16(oacc[p * 2 + 1], a, b1);
            }
        }
    }

    const float inv0 = 1.0f / lrow0, inv1 = 1.0f / lrow1;
    __half* og = o + ((size_t)(b * LL + q0 + wm + lm)) * DD + hh * DH;
    #pragma unroll
    for (int ni = 0; ni < 8; ni++) {
        const int cc = ni * 8 + 2 * lk;
        *reinterpret_cast<__half2*>(og + cc) =
            __floats2half2_rn(oacc[ni][0] * inv0, oacc[ni][1] * inv0);
        *reinterpret_cast<__half2*>(og + (size_t)8 * DD + cc) =
            __floats2half2_rn(oacc[ni][2] * inv1, oacc[ni][3] * inv1);
    }
}

// ---------------- driver ----------------
extern "C" void kernel_launch(void* const* d_in, const int* in_sizes, int n_in,
                              void* d_out, int out_size) {
    const float* x        = (const float*)d_in[0];
    const float* gumbel_u = (const float*)d_in[1];
    const float* ln1_g    = (const float*)d_in[2];
    const float* ln1_b    = (const float*)d_in[3];
    const float* ln2_g    = (const float*)d_in[4];
    const float* ln2_b    = (const float*)d_in[5];
    const float* w_sal    = (const float*)d_in[6];
    const float* b_sal    = (const float*)d_in[7];   // constant shift: cancels, unused
    const float* ipw      = (const float*)d_in[8];
    const float* ipb      = (const float*)d_in[9];
    const float* opw      = (const float*)d_in[10];
    const float* opb      = (const float*)d_in[11];
    const float* w_fc     = (const float*)d_in[12];
    const float* b_fc     = (const float*)d_in[13];
    const float* w_proj   = (const float*)d_in[14];
    const float* b_proj   = (const float*)d_in[15];
    float* out = (float*)d_out;
    (void)b_sal;

    void* p;
    cudaGetSymbolAddress(&p, g_h16);    __half* h16   = (__half*)p;
    cudaGetSymbolAddress(&p, g_kv16);   __half* kv16  = (__half*)p;
    cudaGetSymbolAddress(&p, g_q16);    __half* q16   = (__half*)p;
    cudaGetSymbolAddress(&p, g_k16);    __half* k16   = (__half*)p;
    cudaGetSymbolAddress(&p, g_v16);    __half* v16   = (__half*)p;
    cudaGetSymbolAddress(&p, g_att16);  __half* att16 = (__half*)p;
    cudaGetSymbolAddress(&p, g_x2);     float*  x2    = (float*)p;
    cudaGetSymbolAddress(&p, g_h2_16);  __half* h2_16 = (__half*)p;
    cudaGetSymbolAddress(&p, g_ff16);   __half* ff16  = (__half*)p;
    cudaGetSymbolAddress(&p, g_w16);    __half* w16   = (__half*)p;
    cudaGetSymbolAddress(&p, g_logits); float*  logi  = (float*)p;

    const int FA_SMEM = FA_SMEM_HALFS * 2;   // 55296 bytes
    cudaFuncSetAttribute(fattn16_kernel, cudaFuncAttributeMaxDynamicSharedMemorySize, FA_SMEM);

    // 0. weight prep + logits zeroing
    f2h_all_kernel<<<(W16_TOTAL / 4 + 255) / 256, 256>>>(ipw, opw, w_fc, w_proj, w16);
    cudaMemsetAsync(logi, 0, BB * NB * sizeof(float));
    // 1. LN1 + fused saliency logits (fp16 h out, atomic logits)
    ln1_sal_kernel<<<NTOK, 256>>>(x, ln1_g, ln1_b, w_sal, h16, logi);
    // 2+3. fused selection + gather -> kv16 (reads fp16 h)
    gather_kernel<<<MKV, 256>>>(h16, logi, gumbel_u, kv16);
    // 4. fused QKV projection (fp16 out, 512 threads)
    hgemm_qkv<<<dim3(DD / 128, 64 + 20 + 20), 512>>>(
        h16, kv16, w16 + W16_IPW, ipb, q16, k16, v16);
    // 5. attention (fp16 mma flash, V transposed in-kernel via ldsm4t)
    fattn16_kernel<<<dim3(LL / 128, BB * NH), 256, FA_SMEM>>>(q16, k16, v16, att16);
    // 6. out proj + residual (fp32 out)
    hgemm<true, false, true, false><<<dim3(DD / 128, NTOK / 128), 512>>>(
        att16, w16 + W16_OPW, opb, x, x2, NTOK, DD, DD);
    // 7. LN2 (fp16 out)
    ln2_kernel<<<NTOK, 256>>>(x2, ln2_g, ln2_b, h2_16);
    // 8. FFN up + gelu (NN, fp16 out, fast sigmoid-form gelu)
    hgemm<false, true, false, true><<<dim3(DFFN / 128, NTOK / 128), 512>>>(
        h2_16, w16 + W16_WFC, b_fc, nullptr, ff16, NTOK, DFFN, DD);
    // 9. FFN down + residual (NN, fp32 out) -> out
    hgemm<false, false, true, false><<<dim3(DD / 128, NTOK / 128), 512>>>(
        ff16, w16 + W16_WPROJ, b_proj, x2, out, NTOK, DD, DFFN);
}

// round 17
// speedup vs baseline: 1.0871x; 1.0487x over previous
#include <cuda_runtime.h>
#include <cuda_fp16.h>
#include <math.h>
#include <stdint.h>

// ---------------- problem constants ----------------
#define DD     1024
#define LL     2048
#define BB     4
#define NH     16
#define DH     64
#define SSEL   5
#define WWIN   128
#define BKBLK  32
#define NB     64          // L / BK
#define NTOK   8192        // B*L
#define MKV    2560        // B*S*W
#define NKEY   640         // S*W keys per batch
#define DFFN   4096

// ---------------- scratch (device globals; no allocations allowed) --------
__device__ __half g_h16 [NTOK * DD];
__device__ __half g_kv16[MKV  * DD];
__device__ __half g_q16 [NTOK * DD];
__device__ __half g_k16 [MKV  * DD];
__device__ __half g_v16 [MKV  * DD];
__device__ __half g_att16[NTOK * DD];
__device__ float  g_x2  [NTOK * DD];
__device__ __half g_h2_16[NTOK * DD];
__device__ __half g_ff16 [NTOK * DFFN];
__device__ __half g_w16  [12582912];     // fp16 weights: ipw | opw | w_fc | w_proj
__device__ float  g_logits[BB * NB];

#define W16_IPW   0
#define W16_OPW   3145728
#define W16_WFC   4194304
#define W16_WPROJ 8388608
#define W16_TOTAL 12582912

// ---------------- helpers ----------------
__device__ __forceinline__ void mma_f16(float* d, const uint32_t* a, const uint32_t* b) {
    asm volatile(
        "mma.sync.aligned.m16n8k16.row.col.f32.f16.f16.f32 "
        "{%0,%1,%2,%3}, {%4,%5,%6,%7}, {%8,%9}, {%0,%1,%2,%3};\n"
        : "+f"(d[0]), "+f"(d[1]), "+f"(d[2]), "+f"(d[3])
        : "r"(a[0]), "r"(a[1]), "r"(a[2]), "r"(a[3]), "r"(b[0]), "r"(b[1]));
}

__device__ __forceinline__ void ldsm4(uint32_t& r0, uint32_t& r1, uint32_t& r2, uint32_t& r3,
                                      uint32_t addr) {
    asm volatile("ldmatrix.sync.aligned.m8n8.x4.shared.b16 {%0,%1,%2,%3}, [%4];"
                 : "=r"(r0), "=r"(r1), "=r"(r2), "=r"(r3) : "r"(addr));
}
__device__ __forceinline__ void ldsm4t(uint32_t& r0, uint32_t& r1, uint32_t& r2, uint32_t& r3,
                                       uint32_t addr) {
    asm volatile("ldmatrix.sync.aligned.m8n8.x4.trans.shared.b16 {%0,%1,%2,%3}, [%4];"
                 : "=r"(r0), "=r"(r1), "=r"(r2), "=r"(r3) : "r"(addr));
}

__device__ __forceinline__ void cp16(void* s, const void* g) {
    unsigned sa = (unsigned)__cvta_generic_to_shared(s);
    asm volatile("cp.async.cg.shared.global [%0], [%1], 16;\n" :: "r"(sa), "l"(g));
}
__device__ __forceinline__ void cp_commit() { asm volatile("cp.async.commit_group;\n"); }
__device__ __forceinline__ void cp_wait0()  { asm volatile("cp.async.wait_group 0;\n"); }

// fast gelu: 0.5*v*(1+tanh(u)) == v / (1 + exp(-2u))
__device__ __forceinline__ float gelu_fast(float v) {
    float u = 0.7978845608028654f * (v + 0.044715f * v * v * v);
    return v / (1.0f + __expf(-2.0f * u));
}

// ---------------- fused fp32 -> fp16 weight conversion ----------------
__global__ void f2h_all_kernel(const float* __restrict__ ipw,
                               const float* __restrict__ opw,
                               const float* __restrict__ wfc,
                               const float* __restrict__ wproj,
                               __half* __restrict__ w16) {
    int i = (blockIdx.x * blockDim.x + threadIdx.x) * 4;
    if (i >= W16_TOTAL) return;
    const float* src;
    if (i < W16_OPW)        src = ipw + i;
    else if (i < W16_WFC)   src = opw + (i - W16_OPW);
    else if (i < W16_WPROJ) src = wfc + (i - W16_WFC);
    else                    src = wproj + (i - W16_WPROJ);
    float4 v = *reinterpret_cast<const float4*>(src);
    __half2* d = reinterpret_cast<__half2*>(w16 + i);
    d[0] = __floats2half2_rn(v.x, v.y);
    d[1] = __floats2half2_rn(v.z, v.w);
}

// ---------- LN1 + fused saliency: one block per token ----------
__global__ void ln1_sal_kernel(const float* __restrict__ x,
                               const float* __restrict__ gam,
                               const float* __restrict__ bet,
                               const float* __restrict__ w_sal,
                               __half* __restrict__ out16,
                               float* __restrict__ logits) {
    __shared__ float red[8];
    const int row = blockIdx.x;
    const int t = threadIdx.x;  // 256
    const float4* xr = reinterpret_cast<const float4*>(x) + (size_t)row * (DD / 4);
    float4 v = xr[t];

    float s = v.x + v.y + v.z + v.w;
    #pragma unroll
    for (int o = 16; o; o >>= 1) s += __shfl_down_sync(0xffffffffu, s, o);
    if ((t & 31) == 0) red[t >> 5] = s;
    __syncthreads();
    float tot = red[0] + red[1] + red[2] + red[3] + red[4] + red[5] + red[6] + red[7];
    const float mean = tot * (1.0f / DD);
    __syncthreads();

    float dx = v.x - mean, dy = v.y - mean, dz = v.z - mean, dw = v.w - mean;
    float sq = dx * dx + dy * dy + dz * dz + dw * dw;
    #pragma unroll
    for (int o = 16; o; o >>= 1) sq += __shfl_down_sync(0xffffffffu, sq, o);
    if ((t & 31) == 0) red[t >> 5] = sq;
    __syncthreads();
    float var = (red[0] + red[1] + red[2] + red[3] + red[4] + red[5] + red[6] + red[7]) * (1.0f / DD);
    const float r = rsqrtf(var + 1e-5f);

    const float4 gg = reinterpret_cast<const float4*>(gam)[t];
    const float4 bb = reinterpret_cast<const float4*>(bet)[t];
    float4 o4;
    o4.x = dx * r * gg.x + bb.x;
    o4.y = dy * r * gg.y + bb.y;
    o4.z = dz * r * gg.z + bb.z;
    o4.w = dw * r * gg.w + bb.w;
    __half2* d = reinterpret_cast<__half2*>(out16 + (size_t)row * DD + t * 4);
    d[0] = __floats2half2_rn(o4.x, o4.y);
    d[1] = __floats2half2_rn(o4.z, o4.w);

    const float4 ws = reinterpret_cast<const float4*>(w_sal)[t];
    float dsal = o4.x * ws.x + o4.y * ws.y + o4.z * ws.z + o4.w * ws.w;
    __syncthreads();
    #pragma unroll
    for (int o = 16; o; o >>= 1) dsal += __shfl_down_sync(0xffffffffu, dsal, o);
    if ((t & 31) == 0) red[t >> 5] = dsal;
    __syncthreads();
    if (t == 0) {
        float dtot = red[0] + red[1] + red[2] + red[3] + red[4] + red[5] + red[6] + red[7];
        atomicAdd(&logits[row >> 5], dtot * (1.0f / BKBLK));
    }
}

// ---------------- LayerNorm (LN2): one block per token, fp16 out ----------
__global__ void ln2_kernel(const float* __restrict__ x,
                           const float* __restrict__ gam,
                           const float* __restrict__ bet,
                           __half* __restrict__ out16) {
    __shared__ float red[8];
    const int row = blockIdx.x;
    const int t = threadIdx.x;  // 256
    const float4* xr = reinterpret_cast<const float4*>(x) + (size_t)row * (DD / 4);
    float4 v = xr[t];

    float s = v.x + v.y + v.z + v.w;
    #pragma unroll
    for (int o = 16; o; o >>= 1) s += __shfl_down_sync(0xffffffffu, s, o);
    if ((t & 31) == 0) red[t >> 5] = s;
    __syncthreads();
    float tot = red[0] + red[1] + red[2] + red[3] + red[4] + red[5] + red[6] + red[7];
    const float mean = tot * (1.0f / DD);
    __syncthreads();

    float dx = v.x - mean, dy = v.y - mean, dz = v.z - mean, dw = v.w - mean;
    float sq = dx * dx + dy * dy + dz * dz + dw * dw;
    #pragma unroll
    for (int o = 16; o; o >>= 1) sq += __shfl_down_sync(0xffffffffu, sq, o);
    if ((t & 31) == 0) red[t >> 5] = sq;
    __syncthreads();
    float var = (red[0] + red[1] + red[2] + red[3] + red[4] + red[5] + red[6] + red[7]) * (1.0f / DD);
    const float r = rsqrtf(var + 1e-5f);

    const float4 gg = reinterpret_cast<const float4*>(gam)[t];
    const float4 bb = reinterpret_cast<const float4*>(bet)[t];
    __half2* d = reinterpret_cast<__half2*>(out16 + (size_t)row * DD + t * 4);
    d[0] = __floats2half2_rn(dx * r * gg.x + bb.x, dy * r * gg.y + bb.y);
    d[1] = __floats2half2_rn(dz * r * gg.z + bb.z, dw * r * gg.w + bb.w);
}

// -------- fused selection + window gather (fp16 in/out) --------
__global__ void gather_kernel(const __half* __restrict__ h16,
                              const float* __restrict__ logits,
                              const float* __restrict__ gu,
                              __half* __restrict__ kv) {
    __shared__ int   s_start;
    __shared__ float s_scale;

    const int row = blockIdx.x;          // b*640 + s*128 + w
    const int b = row / (SSEL * WWIN);
    const int r = row % (SSEL * WWIN);
    const int s = r / WWIN;
    const int w = r % WWIN;
    const int sb = s * BB + b;
    const int t = threadIdx.x;           // 256

    if (t < 32) {
        const int lane = t;
        float u0 = gu[sb * NB + lane];
        float u1 = gu[sb * NB + 32 + lane];
        float g0 = -logf(-logf(u0 + 1e-9f) + 1e-9f);
        float g1 = -logf(-logf(u1 + 1e-9f) + 1e-9f);
        float p0 = logits[b * NB + lane] + g0;       // TAU = 1, b_sal shift dropped
        float p1 = logits[b * NB + 32 + lane] + g1;

        float m = p0; int idx = lane;
        if (p1 > m) { m = p1; idx = lane + 32; }
        #pragma unroll
        for (int o = 16; o; o >>= 1) {
            float om = __shfl_down_sync(0xffffffffu, m, o);
            int   oi = __shfl_down_sync(0xffffffffu, idx, o);
            if (om > m || (om == m && oi < idx)) { m = om; idx = oi; }
        }
        m   = __shfl_sync(0xffffffffu, m, 0);
        idx = __shfl_sync(0xffffffffu, idx, 0);

        float se = expf(p0 - m) + expf(p1 - m);
        #pragma unroll
        for (int o = 16; o; o >>= 1) se += __shfl_down_sync(0xffffffffu, se, o);
        if (lane == 0) {
            float ww = 1.0f / se;
            float scale = (1.0f + ww) - ww;
            int start = idx * BKBLK + BKBLK / 2 - WWIN / 2;
            if (start < 0) start = 0;
            if (start > LL - WWIN) start = LL - WWIN;
            s_start = start;
            s_scale = scale;
        }
    }
    __syncthreads();

    const int src = b * LL + s_start + w;
    const __half2 sc2 = __float2half2_rn(s_scale);
    uint2 raw = *reinterpret_cast<const uint2*>(h16 + (size_t)src * DD + t * 4);
    __half2* hp = reinterpret_cast<__half2*>(&raw);
    hp[0] = __hmul2(hp[0], sc2);
    hp[1] = __hmul2(hp[1], sc2);
    *reinterpret_cast<uint2*>(kv + (size_t)row * DD + t * 4) = raw;
}

// ===== FP16 tensor-core GEMM: 512 threads, warp tile 32x32, K-stage 64 =====
#define HAS 72       // A / B-NT smem row stride (halfs); proven conflict-free
#define HBS 136      // B-NN smem row stride (halfs)
#define HSTG 9216    // halfs per tile stage (128 rows x 72 >= 64 rows x 136)
#define GEMM_SMEM (4 * HSTG * 2)   // 73728 bytes dynamic

template<bool BT, bool GELU, bool RES, bool OUTH>
__global__ __launch_bounds__(512, 2)
void hgemm(const __half* __restrict__ A,
           const __half* __restrict__ B,
           const float* __restrict__ bias,
           const float* __restrict__ res,
           void* __restrict__ Cout,
           int M, int N, int K) {
    extern __shared__ __half gsm[];
    const uint32_t sm_u32 = (uint32_t)__cvta_generic_to_shared(gsm);

    const int tid  = threadIdx.x;       // 512
    const int lane = tid & 31;
    const int wid  = tid >> 5;          // 0..15
    const int wm = (wid & 3) * 32;      // 4 warps along M
    const int wn = (wid >> 2) * 32;     // 4 warps along N
    const int lm = lane >> 2;
    const int lk = lane & 3;
    const int m0 = blockIdx.y * 128;
    const int n0 = blockIdx.x * 128;

    float acc[2][4][4];
    #pragma unroll
    for (int i = 0; i < 2; i++)
        #pragma unroll
        for (int j = 0; j < 4; j++)
            #pragma unroll
            for (int f = 0; f < 4; f++) acc[i][j][f] = 0.0f;

    // stage = 64 K-halfs. A tile: 128r x 64c (stride 72). B: BT 128r x 64c (72),
    // NN 64r x 128c (stride 136).
    auto issue = [&](int k0, int buf) {
        __half* As = gsm + (size_t)buf * HSTG;
        __half* Bs = gsm + (size_t)(2 + buf) * HSTG;
        #pragma unroll
        for (int j = 0; j < 2; j++) {
            int idx = tid + j * 512;          // 0..1023
            int r = idx >> 3, c = (idx & 7) * 8;
            cp16(&As[r * HAS + c], A + (size_t)(m0 + r) * K + k0 + c);
        }
        #pragma unroll
        for (int j = 0; j < 2; j++) {
            int idx = tid + j * 512;
            if (BT) {
                int r = idx >> 3, c = (idx & 7) * 8;
                cp16(&Bs[r * HAS + c], B + (size_t)(n0 + r) * K + k0 + c);
            } else {
                int r = idx >> 4, c = (idx & 15) * 8;
                cp16(&Bs[r * HBS + c], B + (size_t)(k0 + r) * N + n0 + c);
            }
        }
    };

    issue(0, 0);
    cp_commit();
    cp_wait0();
    __syncthreads();

    const int a_row  = lane & 15;
    const int a_colh = ((lane >> 4) << 3);
    const int g  = lane >> 3;
    const int lr = lane & 7;
    const int t_krow = ((g >> 1) << 3) + lr;
    const int t_ncol = (g & 1) << 3;

    const int T = K >> 6;   // K / 64
    for (int t = 0; t < T; t++) {
        const int buf = t & 1;
        if (t + 1 < T) { issue((t + 1) << 6, buf ^ 1); cp_commit(); }

        const uint32_t Au = sm_u32 + 2u * (uint32_t)(buf * HSTG);
        const uint32_t Bu = sm_u32 + 2u * (uint32_t)((2 + buf) * HSTG);

        #pragma unroll
        for (int ks = 0; ks < 4; ks++) {
            uint32_t a[2][4];
            #pragma unroll
            for (int mi = 0; mi < 2; mi++) {
                uint32_t addr = Au + 2 * ((wm + mi * 16 + a_row) * HAS + ks * 16 + a_colh);
                ldsm4(a[mi][0], a[mi][1], a[mi][2], a[mi][3], addr);
            }
            uint32_t b[4][2];
            #pragma unroll
            for (int p = 0; p < 2; p++) {
                uint32_t r0, r1, r2, r3;
                if (BT) {
                    uint32_t addr = Bu + 2 * ((wn + p * 16 + a_row) * HAS + ks * 16 + a_colh);
                    ldsm4(r0, r1, r2, r3, addr);
                } else {
                    uint32_t addr = Bu + 2 * ((ks * 16 + t_krow) * HBS + wn + p * 16 + t_ncol);
                    ldsm4t(r0, r1, r2, r3, addr);
                }
                b[p * 2 + 0][0] = r0; b[p * 2 + 0][1] = r2;
                b[p * 2 + 1][0] = r1; b[p * 2 + 1][1] = r3;
            }
            #pragma unroll
            for (int mi = 0; mi < 2; mi++)
                #pragma unroll
                for (int ni = 0; ni < 4; ni++)
                    mma_f16(acc[mi][ni], a[mi], b[ni]);
        }

        if (t + 1 < T) { cp_wait0(); __syncthreads(); }
    }

    #pragma unroll
    for (int ni = 0; ni < 4; ni++) {
        const int cn = n0 + wn + ni * 8 + lk * 2;
        const float bx = bias[cn], by = bias[cn + 1];
        #pragma unroll
        for (int mi = 0; mi < 2; mi++) {
            const int rm = m0 + wm + mi * 16 + lm;
            float v0 = acc[mi][ni][0] + bx;
            float v1 = acc[mi][ni][1] + by;
            float v2 = acc[mi][ni][2] + bx;
            float v3 = acc[mi][ni][3] + by;
            if (GELU) {
                v0 = gelu_fast(v0); v1 = gelu_fast(v1);
                v2 = gelu_fast(v2); v3 = gelu_fast(v3);
            }
            if (RES) {
                const float* rf = (const float*)res;
                float2 r0 = *reinterpret_cast<const float2*>(rf + (size_t)rm * N + cn);
                float2 r1 = *reinterpret_cast<const float2*>(rf + (size_t)(rm + 8) * N + cn);
                v0 += r0.x; v1 += r0.y; v2 += r1.x; v3 += r1.y;
            }
            if (OUTH) {
                __half* C = (__half*)Cout;
                *reinterpret_cast<__half2*>(C + (size_t)rm * N + cn) = __floats2half2_rn(v0, v1);
                *reinterpret_cast<__half2*>(C + (size_t)(rm + 8) * N + cn) = __floats2half2_rn(v2, v3);
            } else {
                float* C = (float*)Cout;
                float2 o0 = {v0, v1}, o1 = {v2, v3};
                *reinterpret_cast<float2*>(C + (size_t)rm * N + cn) = o0;
                *reinterpret_cast<float2*>(C + (size_t)(rm + 8) * N + cn) = o1;
            }
        }
    }
}

// ====== fused QKV GEMM (NT, fp16 out), 512 threads, K-stage 64 =============
__global__ __launch_bounds__(512, 2)
void hgemm_qkv(const __half* __restrict__ h16,
               const __half* __restrict__ kv16,
               const __half* __restrict__ ipw16,
               const float* __restrict__ ipb,
               __half* __restrict__ qo,
               __half* __restrict__ ko,
               __half* __restrict__ vo) {
    extern __shared__ __half gsm[];
    const uint32_t sm_u32 = (uint32_t)__cvta_generic_to_shared(gsm);

    const int y = blockIdx.y;
    int seg, my;
    if (y < 64)      { seg = 0; my = y; }
    else if (y < 84) { seg = 1; my = y - 64; }
    else             { seg = 2; my = y - 84; }
    const __half* A = (seg == 0) ? h16 : kv16;
    const __half* B = ipw16 + (size_t)seg * DD * DD;
    const float* bias = ipb + seg * DD;
    __half* C = (seg == 0) ? qo : ((seg == 1) ? ko : vo);
    const int K = DD, N = DD;
    const int m0 = my * 128;
    const int n0 = blockIdx.x * 128;

    const int tid  = threadIdx.x;       // 512
    const int lane = tid & 31;
    const int wid  = tid >> 5;
    const int wm = (wid & 3) * 32;
    const int wn = (wid >> 2) * 32;
    const int lm = lane >> 2;
    const int lk = lane & 3;

    float acc[2][4][4];
    #pragma unroll
    for (int i = 0; i < 2; i++)
        #pragma unroll
        for (int j = 0; j < 4; j++)
            #pragma unroll
            for (int f = 0; f < 4; f++) acc[i][j][f] = 0.0f;

    auto issue = [&](int k0, int buf) {
        __half* As = gsm + (size_t)buf * HSTG;
        __half* Bs = gsm + (size_t)(2 + buf) * HSTG;
        #pragma unroll
        for (int j = 0; j < 2; j++) {
            int idx = tid + j * 512;
            int r = idx >> 3, c = (idx & 7) * 8;
            cp16(&As[r * HAS + c], A + (size_t)(m0 + r) * K + k0 + c);
        }
        #pragma unroll
        for (int j = 0; j < 2; j++) {
            int idx = tid + j * 512;
            int r = idx >> 3, c = (idx & 7) * 8;
            cp16(&Bs[r * HAS + c], B + (size_t)(n0 + r) * K + k0 + c);
        }
    };

    issue(0, 0);
    cp_commit();
    cp_wait0();
    __syncthreads();

    const int a_row  = lane & 15;
    const int a_colh = ((lane >> 4) << 3);

    const int T = K >> 6;
    for (int t = 0; t < T; t++) {
        const int buf = t & 1;
        if (t + 1 < T) { issue((t + 1) << 6, buf ^ 1); cp_commit(); }

        const uint32_t Au = sm_u32 + 2u * (uint32_t)(buf * HSTG);
        const uint32_t Bu = sm_u32 + 2u * (uint32_t)((2 + buf) * HSTG);

        #pragma unroll
        for (int ks = 0; ks < 4; ks++) {
            uint32_t a[2][4];
            #pragma unroll
            for (int mi = 0; mi < 2; mi++) {
                uint32_t addr = Au + 2 * ((wm + mi * 16 + a_row) * HAS + ks * 16 + a_colh);
                ldsm4(a[mi][0], a[mi][1], a[mi][2], a[mi][3], addr);
            }
            uint32_t b[4][2];
            #pragma unroll
            for (int p = 0; p < 2; p++) {
                uint32_t r0, r1, r2, r3;
                uint32_t addr = Bu + 2 * ((wn + p * 16 + a_row) * HAS + ks * 16 + a_colh);
                ldsm4(r0, r1, r2, r3, addr);
                b[p * 2 + 0][0] = r0; b[p * 2 + 0][1] = r2;
                b[p * 2 + 1][0] = r1; b[p * 2 + 1][1] = r3;
            }
            #pragma unroll
            for (int mi = 0; mi < 2; mi++)
                #pragma unroll
                for (int ni = 0; ni < 4; ni++)
                    mma_f16(acc[mi][ni], a[mi], b[ni]);
        }

        if (t + 1 < T) { cp_wait0(); __syncthreads(); }
    }

    #pragma unroll
    for (int ni = 0; ni < 4; ni++) {
        const int cn = n0 + wn + ni * 8 + lk * 2;
        const float bx = bias[cn], by = bias[cn + 1];
        #pragma unroll
        for (int mi = 0; mi < 2; mi++) {
            const int rm = m0 + wm + mi * 16 + lm;
            *reinterpret_cast<__half2*>(C + (size_t)rm * N + cn) =
                __floats2half2_rn(acc[mi][ni][0] + bx, acc[mi][ni][1] + by);
            *reinterpret_cast<__half2*>(C + (size_t)(rm + 8) * N + cn) =
                __floats2half2_rn(acc[mi][ni][2] + bx, acc[mi][ni][3] + by);
        }
    }
}

// ====== flash attention: fp16 mma, 128 q/block, V via ldsm4t (no vtrans) ====
#define FA_STR 72   // halfs per smem row (64 + 8 pad); row pitch 144B
#define FA_Q_OFF 0
#define FA_K_OFF (128 * FA_STR)
#define FA_V_OFF (192 * FA_STR)
#define FA_P_OFF (256 * FA_STR)
#define FA_SMEM_HALFS (384 * FA_STR)

__global__ __launch_bounds__(256)
void fattn16_kernel(const __half* __restrict__ q,
                    const __half* __restrict__ k,
                    const __half* __restrict__ v,
                    __half* __restrict__ o) {
    extern __shared__ __half fsm[];
    __half* Qh = fsm + FA_Q_OFF;
    __half* Kh = fsm + FA_K_OFF;
    __half* Vh = fsm + FA_V_OFF;   // natural [j][d] layout
    __half* Ph = fsm + FA_P_OFF;
    const uint32_t base_u = (uint32_t)__cvta_generic_to_shared(fsm);
    const uint32_t Qu = base_u + 2 * FA_Q_OFF;
    const uint32_t Ku = base_u + 2 * FA_K_OFF;
    const uint32_t Vu = base_u + 2 * FA_V_OFF;
    const uint32_t Pu = base_u + 2 * FA_P_OFF;

    const int bh = blockIdx.y;
    const int b = bh >> 4, hh = bh & 15;
    const int q0 = blockIdx.x * 128;
    const int tid = threadIdx.x, lane = tid & 31, wid = tid >> 5;
    const int lm = lane >> 2, lk = lane & 3;
    const int wm = wid * 16;   // 8 warps -> 128 query rows

    const int a_row  = lane & 15;
    const int a_colh = ((lane >> 4) << 3);
    const int g  = lane >> 3;
    const int lr = lane & 7;
    const int t_krow = ((g >> 1) << 3) + lr;
    const int t_ncol = (g & 1) << 3;

    // load Q tile: 128 rows (scaled by 1/8, exact in fp16)
    {
        const __half2 sc = __floats2half2_rn(0.125f, 0.125f);
        const __half* qg = q + ((size_t)(b * LL + q0)) * DD + hh * DH;
        #pragma unroll
        for (int it = 0; it < 4; it++) {
            int idx = tid + it * 256;          // 0..1023
            int r = idx >> 3, c = (idx & 7) * 8;
            uint4 raw = *reinterpret_cast<const uint4*>(qg + (size_t)r * DD + c);
            __half2* hp = reinterpret_cast<__half2*>(&raw);
            hp[0] = __hmul2(hp[0], sc); hp[1] = __hmul2(hp[1], sc);
            hp[2] = __hmul2(hp[2], sc); hp[3] = __hmul2(hp[3], sc);
            *reinterpret_cast<uint4*>(&Qh[r * FA_STR + c]) = raw;
        }
    }

    float mrow0 = -1e30f, mrow1 = -1e30f, lrow0 = 0.0f, lrow1 = 0.0f;
    float oacc[8][4];
    #pragma unroll
    for (int ni = 0; ni < 8; ni++)
        #pragma unroll
        for (int f = 0; f < 4; f++) oacc[ni][f] = 0.0f;

    const __half* kg = k + ((size_t)(b * NKEY)) * DD + hh * DH;
    const __half* vg = v + ((size_t)(b * NKEY)) * DD + hh * DH;

    for (int kt = 0; kt < NKEY / 64; kt++) {
        __syncthreads();
        #pragma unroll
        for (int it = 0; it < 2; it++) {
            int idx = tid + it * 256;
            int r = idx >> 3, c = (idx & 7) * 8;
            *reinterpret_cast<uint4*>(&Kh[r * FA_STR + c]) =
                *reinterpret_cast<const uint4*>(kg + (size_t)(kt * 64 + r) * DD + c);
            *reinterpret_cast<uint4*>(&Vh[r * FA_STR + c]) =
                *reinterpret_cast<const uint4*>(vg + (size_t)(kt * 64 + r) * DD + c);
        }
        __syncthreads();

        // S = Q @ K^T (fp16 mma)
        float s[8][4];
        #pragma unroll
        for (int ni = 0; ni < 8; ni++)
            #pragma unroll
            for (int f = 0; f < 4; f++) s[ni][f] = 0.0f;

        #pragma unroll
        for (int kk = 0; kk < 4; kk++) {
            uint32_t a[4];
            ldsm4(a[0], a[1], a[2], a[3],
                  Qu + 2 * ((wm + a_row) * FA_STR + kk * 16 + a_colh));
            #pragma unroll
            for (int p = 0; p < 4; p++) {
                uint32_t r0, r1, r2, r3;
                ldsm4(r0, r1, r2, r3,
                      Ku + 2 * ((p * 16 + a_row) * FA_STR + kk * 16 + a_colh));
                uint32_t b0[2] = {r0, r2}, b1[2] = {r1, r3};
                mma_f16(s[p * 2 + 0], a, b0);
                mma_f16(s[p * 2 + 1], a, b1);
            }
        }

        // online softmax (rows lm, lm+8)
        float rm0 = -1e30f, rm1 = -1e30f;
        #pragma unroll
        for (int ni = 0; ni < 8; ni++) {
            rm0 = fmaxf(rm0, fmaxf(s[ni][0], s[ni][1]));
            rm1 = fmaxf(rm1, fmaxf(s[ni][2], s[ni][3]));
        }
        rm0 = fmaxf(rm0, __shfl_xor_sync(0xffffffffu, rm0, 1));
        rm0 = fmaxf(rm0, __shfl_xor_sync(0xffffffffu, rm0, 2));
        rm1 = fmaxf(rm1, __shfl_xor_sync(0xffffffffu, rm1, 1));
        rm1 = fmaxf(rm1, __shfl_xor_sync(0xffffffffu, rm1, 2));

        float nm0 = fmaxf(mrow0, rm0), nm1 = fmaxf(mrow1, rm1);
        float al0 = __expf(mrow0 - nm0), al1 = __expf(mrow1 - nm1);
        mrow0 = nm0; mrow1 = nm1;

        float rs0 = 0.0f, rs1 = 0.0f;
        #pragma unroll
        for (int ni = 0; ni < 8; ni++) {
            s[ni][0] = __expf(s[ni][0] - nm0);
            s[ni][1] = __expf(s[ni][1] - nm0);
            s[ni][2] = __expf(s[ni][2] - nm1);
            s[ni][3] = __expf(s[ni][3] - nm1);
            rs0 += s[ni][0] + s[ni][1];
            rs1 += s[ni][2] + s[ni][3];
        }
        rs0 += __shfl_xor_sync(0xffffffffu, rs0, 1);
        rs0 += __shfl_xor_sync(0xffffffffu, rs0, 2);
        rs1 += __shfl_xor_sync(0xffffffffu, rs1, 1);
        rs1 += __shfl_xor_sync(0xffffffffu, rs1, 2);

        lrow0 = lrow0 * al0 + rs0;
        lrow1 = lrow1 * al1 + rs1;

        #pragma unroll
        for (int ni = 0; ni < 8; ni++) {
            oacc[ni][0] *= al0; oacc[ni][1] *= al0;
            oacc[ni][2] *= al1; oacc[ni][3] *= al1;
        }

        // P -> smem fp16 (own warp rows only)
        #pragma unroll
        for (int ni = 0; ni < 8; ni++) {
            __half* pp = &Ph[(wm + lm) * FA_STR + ni * 8 + 2 * lk];
            *reinterpret_cast<__half2*>(pp) = __floats2half2_rn(s[ni][0], s[ni][1]);
            *reinterpret_cast<__half2*>(pp + 8 * FA_STR) = __floats2half2_rn(s[ni][2], s[ni][3]);
        }
        __syncwarp();

        // O += P @ V : Vh is [j][d] = [K][N] row-major -> ldsm4t (hgemm NN idiom)
        #pragma unroll
        for (int kk = 0; kk < 4; kk++) {
            uint32_t a[4];
            ldsm4(a[0], a[1], a[2], a[3],
                  Pu + 2 * ((wm + a_row) * FA_STR + kk * 16 + a_colh));
            #pragma unroll
            for (int p = 0; p < 4; p++) {
                uint32_t r0, r1, r2, r3;
                ldsm4t(r0, r1, r2, r3,
                       Vu + 2 * ((kk * 16 + t_krow) * FA_STR + p * 16 + t_ncol));
                uint32_t b0[2] = {r0, r2}, b1[2] = {r1, r3};
                mma_f16(oacc[p * 2 + 0], a, b0);
                mma_f16(oacc[p * 2 + 1], a, b1);
            }
        }
    }

    const float inv0 = 1.0f / lrow0, inv1 = 1.0f / lrow1;
    __half* og = o + ((size_t)(b * LL + q0 + wm + lm)) * DD + hh * DH;
    #pragma unroll
    for (int ni = 0; ni < 8; ni++) {
        const int cc = ni * 8 + 2 * lk;
        *reinterpret_cast<__half2*>(og + cc) =
            __floats2half2_rn(oacc[ni][0] * inv0, oacc[ni][1] * inv0);
        *reinterpret_cast<__half2*>(og + (size_t)8 * DD + cc) =
            __floats2half2_rn(oacc[ni][2] * inv1, oacc[ni][3] * inv1);
    }
}

// ---------------- driver ----------------
extern "C" void kernel_launch(void* const* d_in, const int* in_sizes, int n_in,
                              void* d_out, int out_size) {
    const float* x        = (const float*)d_in[0];
    const float* gumbel_u = (const float*)d_in[1];
    const float* ln1_g    = (const float*)d_in[2];
    const float* ln1_b    = (const float*)d_in[3];
    const float* ln2_g    = (const float*)d_in[4];
    const float* ln2_b    = (const float*)d_in[5];
    const float* w_sal    = (const float*)d_in[6];
    const float* b_sal    = (const float*)d_in[7];   // constant shift: cancels, unused
    const float* ipw      = (const float*)d_in[8];
    const float* ipb      = (const float*)d_in[9];
    const float* opw      = (const float*)d_in[10];
    const float* opb      = (const float*)d_in[11];
    const float* w_fc     = (const float*)d_in[12];
    const float* b_fc     = (const float*)d_in[13];
    const float* w_proj   = (const float*)d_in[14];
    const float* b_proj   = (const float*)d_in[15];
    float* out = (float*)d_out;
    (void)b_sal;

    void* p;
    cudaGetSymbolAddress(&p, g_h16);    __half* h16   = (__half*)p;
    cudaGetSymbolAddress(&p, g_kv16);   __half* kv16  = (__half*)p;
    cudaGetSymbolAddress(&p, g_q16);    __half* q16   = (__half*)p;
    cudaGetSymbolAddress(&p, g_k16);    __half* k16   = (__half*)p;
    cudaGetSymbolAddress(&p, g_v16);    __half* v16   = (__half*)p;
    cudaGetSymbolAddress(&p, g_att16);  __half* att16 = (__half*)p;
    cudaGetSymbolAddress(&p, g_x2);     float*  x2    = (float*)p;
    cudaGetSymbolAddress(&p, g_h2_16);  __half* h2_16 = (__half*)p;
    cudaGetSymbolAddress(&p, g_ff16);   __half* ff16  = (__half*)p;
    cudaGetSymbolAddress(&p, g_w16);    __half* w16   = (__half*)p;
    cudaGetSymbolAddress(&p, g_logits); float*  logi  = (float*)p;

    const int FA_SMEM = FA_SMEM_HALFS * 2;   // 55296 bytes
    cudaFuncSetAttribute(fattn16_kernel, cudaFuncAttributeMaxDynamicSharedMemorySize, FA_SMEM);
    cudaFuncSetAttribute(hgemm<true,  false, true,  false>, cudaFuncAttributeMaxDynamicSharedMemorySize, GEMM_SMEM);
    cudaFuncSetAttribute(hgemm<false, true,  false, true >, cudaFuncAttributeMaxDynamicSharedMemorySize, GEMM_SMEM);
    cudaFuncSetAttribute(hgemm<false, false, true,  false>, cudaFuncAttributeMaxDynamicSharedMemorySize, GEMM_SMEM);
    cudaFuncSetAttribute(hgemm_qkv, cudaFuncAttributeMaxDynamicSharedMemorySize, GEMM_SMEM);

    // 0. weight prep + logits zeroing
    f2h_all_kernel<<<(W16_TOTAL / 4 + 255) / 256, 256>>>(ipw, opw, w_fc, w_proj, w16);
    cudaMemsetAsync(logi, 0, BB * NB * sizeof(float));
    // 1. LN1 + fused saliency logits (fp16 h out, atomic logits)
    ln1_sal_kernel<<<NTOK, 256>>>(x, ln1_g, ln1_b, w_sal, h16, logi);
    // 2+3. fused selection + gather -> kv16 (reads fp16 h)
    gather_kernel<<<MKV, 256>>>(h16, logi, gumbel_u, kv16);
    // 4. fused QKV projection (fp16 out, 512 threads, K-stage 64)
    hgemm_qkv<<<dim3(DD / 128, 64 + 20 + 20), 512, GEMM_SMEM>>>(
        h16, kv16, w16 + W16_IPW, ipb, q16, k16, v16);
    // 5. attention (fp16 mma flash, V transposed in-kernel via ldsm4t)
    fattn16_kernel<<<dim3(LL / 128, BB * NH), 256, FA_SMEM>>>(q16, k16, v16, att16);
    // 6. out proj + residual (fp32 out)
    hgemm<true, false, true, false><<<dim3(DD / 128, NTOK / 128), 512, GEMM_SMEM>>>(
        att16, w16 + W16_OPW, opb, x, x2, NTOK, DD, DD);
    // 7. LN2 (fp16 out)
    ln2_kernel<<<NTOK, 256>>>(x2, ln2_g, ln2_b, h2_16);
    // 8. FFN up + gelu (NN, fp16 out, fast sigmoid-form gelu)
    hgemm<false, true, false, true><<<dim3(DFFN / 128, NTOK / 128), 512, GEMM_SMEM>>>(
        h2_16, w16 + W16_WFC, b_fc, nullptr, ff16, NTOK, DFFN, DD);
    // 9. FFN down + residual (NN, fp32 out) -> out
    hgemm<false, false, true, false><<<dim3(DD / 128, NTOK / 128), 512, GEMM_SMEM>>>(
        ff16, w16 + W16_WPROJ, b_proj, x2, out, NTOK, DD, DFFN);
}